// round 2
// baseline (speedup 1.0000x reference)
#include <cuda_runtime.h>
#include <math.h>

// Problem dims (fixed)
#define NB 96
#define NQ 96
#define NV 197
#define NT 77
#define ND 768
#define NE 512

// L2-resident scratch for projected+normalized tokens (fp32 this round; bf16 later)
__device__ float g_vtok[(size_t)NB * NV * NE];   // 38.7 MB
__device__ float g_ttok[(size_t)NQ * NT * NE];   // 15.1 MB

// ---------------------------------------------------------------------------
// Projection GEMM: Y[r,e] = sum_d X[r,d] * W[e,d] + bias[e]
// Both operands K-contiguous (NT-GEMM). BM=BN=64, BK=16, 256 thr, 4x4/thread.
// ---------------------------------------------------------------------------
__global__ __launch_bounds__(256) void proj_gemm(
    const float* __restrict__ X, const float* __restrict__ W,
    const float* __restrict__ bias, float* __restrict__ Y, int R)
{
    __shared__ float As[16][68];   // [k][row], padded
    __shared__ float Bs[16][68];   // [k][col]
    const int r0 = blockIdx.x * 64;
    const int e0 = blockIdx.y * 64;
    const int tid = threadIdx.x;
    const int ty = tid >> 4, tx = tid & 15;
    const int lrow = tid >> 2, lk4 = tid & 3;

    float acc[4][4];
#pragma unroll
    for (int i = 0; i < 4; i++)
#pragma unroll
        for (int j = 0; j < 4; j++) acc[i][j] = 0.f;

    const int r_ld = r0 + lrow;
    const float4 zero4 = make_float4(0.f, 0.f, 0.f, 0.f);

    for (int k0 = 0; k0 < ND; k0 += 16) {
        float4 av = (r_ld < R)
            ? *(const float4*)(X + (size_t)r_ld * ND + k0 + lk4 * 4) : zero4;
        float4 bv = *(const float4*)(W + (size_t)(e0 + lrow) * ND + k0 + lk4 * 4);
        __syncthreads();
        As[lk4 * 4 + 0][lrow] = av.x; As[lk4 * 4 + 1][lrow] = av.y;
        As[lk4 * 4 + 2][lrow] = av.z; As[lk4 * 4 + 3][lrow] = av.w;
        Bs[lk4 * 4 + 0][lrow] = bv.x; Bs[lk4 * 4 + 1][lrow] = bv.y;
        Bs[lk4 * 4 + 2][lrow] = bv.z; Bs[lk4 * 4 + 3][lrow] = bv.w;
        __syncthreads();
#pragma unroll
        for (int kk = 0; kk < 16; kk++) {
            float4 a = *(const float4*)&As[kk][ty * 4];
            float4 b = *(const float4*)&Bs[kk][tx * 4];
            float aa[4] = {a.x, a.y, a.z, a.w};
            float bb[4] = {b.x, b.y, b.z, b.w};
#pragma unroll
            for (int i = 0; i < 4; i++)
#pragma unroll
                for (int j = 0; j < 4; j++)
                    acc[i][j] = fmaf(aa[i], bb[j], acc[i][j]);
        }
    }
#pragma unroll
    for (int i = 0; i < 4; i++) {
        int r = r0 + ty * 4 + i;
        if (r < R) {
#pragma unroll
            for (int j = 0; j < 4; j++) {
                int e = e0 + tx * 4 + j;
                Y[(size_t)r * NE + e] = acc[i][j] + bias[e];
            }
        }
    }
}

// ---------------------------------------------------------------------------
// L2-normalize rows of both token scratch buffers (one warp per 512-f row)
// ---------------------------------------------------------------------------
__global__ __launch_bounds__(256) void l2norm_rows()
{
    const int NROWS_V = NB * NV;           // 18912
    const int NROWS = NROWS_V + NQ * NT;   // 26304
    int row = blockIdx.x * 8 + (threadIdx.x >> 5);
    int lane = threadIdx.x & 31;
    if (row >= NROWS) return;
    float* p = (row < NROWS_V) ? (g_vtok + (size_t)row * NE)
                               : (g_ttok + (size_t)(row - NROWS_V) * NE);
    float4* p4 = (float4*)p;
    float s = 0.f;
#pragma unroll
    for (int i = lane; i < NE / 4; i += 32) {
        float4 v = p4[i];
        s += v.x * v.x + v.y * v.y + v.z * v.z + v.w * v.w;
    }
#pragma unroll
    for (int off = 16; off > 0; off >>= 1)
        s += __shfl_xor_sync(0xffffffffu, s, off);
    float inv = 1.f / fmaxf(sqrtf(s), 1e-12f);
#pragma unroll
    for (int i = lane; i < NE / 4; i += 32) {
        float4 v = p4[i];
        v.x *= inv; v.y *= inv; v.z *= inv; v.w *= inv;
        p4[i] = v;
    }
}

// ---------------------------------------------------------------------------
// Stage 2: per-(b,q) CTA computes the 197x77 logits tile in SMEM
// (GEMM 197x77x512 with 64x80 chunks, 8x5 per thread, 128 threads),
// then does the masked max/sum reductions entirely on-chip.
// ---------------------------------------------------------------------------
#define LW 81                          // logits row pitch (odd -> conflict-free)
#define LOGITS_FLOATS 15960            // NV*LW=15957 rounded up to x4 (16B align)

__global__ __launch_bounds__(128) void stage2(
    const int* __restrict__ text_length,
    float* __restrict__ t2v, float* __restrict__ v2t)
{
    extern __shared__ float sm[];
    float* logits = sm;                   // NV * LW (15957 used)
    float* As = sm + LOGITS_FLOATS;       // 16 * 68  [k][v]  (16B-aligned base)
    float* Bs = As + 16 * 68;             // 16 * 84  [k][t]

    const int q = blockIdx.x, b = blockIdx.y;
    const float* Va = g_vtok + (size_t)b * NV * NE;
    const float* Tt = g_ttok + (size_t)q * NT * NE;
    const int tid = threadIdx.x;
    const int ty = tid >> 4, tx = tid & 15;   // ty 0..7 (v), tx 0..15 (t)
    const float4 zero4 = make_float4(0.f, 0.f, 0.f, 0.f);

    for (int c0 = 0; c0 < 256; c0 += 64) {    // 4 v-chunks of 64 (pad > 197)
        float acc[8][5];
#pragma unroll
        for (int i = 0; i < 8; i++)
#pragma unroll
            for (int j = 0; j < 5; j++) acc[i][j] = 0.f;

        for (int k0 = 0; k0 < NE; k0 += 16) {
            float4 av[2], bv[3];
#pragma unroll
            for (int it = 0; it < 2; it++) {          // A tile 64x16 = 256 f4
                int idx = it * 128 + tid;
                int ar = idx >> 2, ak = idx & 3;
                int v = c0 + ar;
                av[it] = (v < NV)
                    ? *(const float4*)(Va + (size_t)v * NE + k0 + ak * 4) : zero4;
            }
#pragma unroll
            for (int it = 0; it < 3; it++) {          // B tile 80x16 = 320 f4
                int idx = it * 128 + tid;
                bv[it] = zero4;
                if (idx < 320) {
                    int tr = idx >> 2, bk = idx & 3;
                    if (tr < NT)
                        bv[it] = *(const float4*)(Tt + (size_t)tr * NE + k0 + bk * 4);
                }
            }
            __syncthreads();
#pragma unroll
            for (int it = 0; it < 2; it++) {
                int idx = it * 128 + tid;
                int ar = idx >> 2, ak = idx & 3;
                As[(ak * 4 + 0) * 68 + ar] = av[it].x;
                As[(ak * 4 + 1) * 68 + ar] = av[it].y;
                As[(ak * 4 + 2) * 68 + ar] = av[it].z;
                As[(ak * 4 + 3) * 68 + ar] = av[it].w;
            }
#pragma unroll
            for (int it = 0; it < 3; it++) {
                int idx = it * 128 + tid;
                if (idx < 320) {
                    int tr = idx >> 2, bk = idx & 3;
                    Bs[(bk * 4 + 0) * 84 + tr] = bv[it].x;
                    Bs[(bk * 4 + 1) * 84 + tr] = bv[it].y;
                    Bs[(bk * 4 + 2) * 84 + tr] = bv[it].z;
                    Bs[(bk * 4 + 3) * 84 + tr] = bv[it].w;
                }
            }
            __syncthreads();
#pragma unroll
            for (int kk = 0; kk < 16; kk++) {
                float4 a0 = *(const float4*)(As + kk * 68 + ty * 8);
                float4 a1 = *(const float4*)(As + kk * 68 + ty * 8 + 4);
                float aa[8] = {a0.x, a0.y, a0.z, a0.w, a1.x, a1.y, a1.z, a1.w};
                float bb[5];
#pragma unroll
                for (int j = 0; j < 5; j++) bb[j] = Bs[kk * 84 + tx * 5 + j];
#pragma unroll
                for (int i = 0; i < 8; i++)
#pragma unroll
                    for (int j = 0; j < 5; j++)
                        acc[i][j] = fmaf(aa[i], bb[j], acc[i][j]);
            }
        }
        // spill chunk to logits SMEM (only real v rows)
#pragma unroll
        for (int i = 0; i < 8; i++) {
            int v = c0 + ty * 8 + i;
            if (v < NV) {
#pragma unroll
                for (int j = 0; j < 5; j++)
                    logits[v * LW + tx * 5 + j] = acc[i][j];
            }
        }
    }
    __syncthreads();

    const int len = text_length[q];
    float p_t2v = 0.f, p_v2t = 0.f;

    // t2v: per valid text token t<len, max over all 197 v; sum; /len
    if (tid < NT) {
        float m = -INFINITY;
        for (int v = 0; v < NV; v++) m = fmaxf(m, logits[v * LW + tid]);
        if (tid < len) p_t2v = m;
    }
    // v2t: per v, max over t of masked logit (t>=len contributes 0.0); sum; /197
    for (int v = tid; v < NV; v += 128) {
        float m = -INFINITY;
        for (int t = 0; t < NT; t++) {
            float val = (t < len) ? logits[v * LW + t] : 0.f;
            m = fmaxf(m, val);
        }
        p_v2t += m;
    }
    __syncthreads();
    logits[tid] = p_t2v;
    logits[128 + tid] = p_v2t;
    __syncthreads();
#pragma unroll
    for (int s = 64; s > 0; s >>= 1) {
        if (tid < s) {
            logits[tid] += logits[tid + s];
            logits[128 + tid] += logits[128 + tid + s];
        }
        __syncthreads();
    }
    if (tid == 0) {
        t2v[b * NQ + q] = logits[0] / (float)len;
        v2t[b * NQ + q] = logits[128] / (float)NV;
    }
}

// ---------------------------------------------------------------------------
extern "C" void kernel_launch(void* const* d_in, const int* in_sizes, int n_in,
                              void* d_out, int out_size)
{
    const float* visual_cls     = (const float*)d_in[0];
    const float* visual_tokens  = (const float*)d_in[1];
    const float* textual_cls    = (const float*)d_in[2];
    const float* textual_tokens = (const float*)d_in[3];
    const float* Wv_cls = (const float*)d_in[4];
    const float* bv_cls = (const float*)d_in[5];
    const float* Wt_cls = (const float*)d_in[6];
    const float* bt_cls = (const float*)d_in[7];
    const float* Wv_tok = (const float*)d_in[8];
    const float* bv_tok = (const float*)d_in[9];
    const float* Wt_tok = (const float*)d_in[10];
    const float* bt_tok = (const float*)d_in[11];
    const int*   text_length = (const int*)d_in[12];

    float* out = (float*)d_out;
    float* o_vcls = out;                         // [96,512]
    float* o_tcls = out + NB * NE;               // [96,512]
    float* o_t2v  = out + 2 * NB * NE;           // [96,96]
    float* o_v2t  = o_t2v + NB * NQ;             // [96,96]

    float *pv, *pt;
    cudaGetSymbolAddress((void**)&pv, g_vtok);
    cudaGetSymbolAddress((void**)&pt, g_ttok);

    // Stage 1: projections
    proj_gemm<<<dim3(2, 8), 256>>>(visual_cls, Wv_cls, bv_cls, o_vcls, NB);
    proj_gemm<<<dim3(2, 8), 256>>>(textual_cls, Wt_cls, bt_cls, o_tcls, NQ);
    proj_gemm<<<dim3((NB * NV + 63) / 64, 8), 256>>>(visual_tokens, Wv_tok, bv_tok, pv, NB * NV);
    proj_gemm<<<dim3((NQ * NT + 63) / 64, 8), 256>>>(textual_tokens, Wt_tok, bt_tok, pt, NQ * NT);

    // Stage 1b: l2 normalize token rows
    l2norm_rows<<<(NB * NV + NQ * NT + 7) / 8, 256>>>();

    // Stage 2: fused similarity GEMM + masked max/sum reductions
    size_t smem = (size_t)(LOGITS_FLOATS + 16 * 68 + 16 * 84) * sizeof(float);
    cudaFuncSetAttribute(stage2, cudaFuncAttributeMaxDynamicSharedMemorySize, (int)smem);
    stage2<<<dim3(NQ, NB), 128, smem>>>(text_length, o_t2v, o_v2t);
}

// round 4
// speedup vs baseline: 3.4059x; 3.4059x over previous
#include <cuda_runtime.h>
#include <cuda_bf16.h>
#include <math.h>
#include <stdint.h>

// Problem dims (fixed)
#define NB 96
#define NQ 96
#define NV 197
#define NT 77
#define ND 768
#define NE 512

// Scratch: fp32 projection outputs, then bf16 normalized operands (L2-resident)
__device__ float         g_vtok_f32[(size_t)NB * NV * NE];   // 38.7 MB
__device__ float         g_ttok_f32[(size_t)NQ * NT * NE];   // 15.1 MB
__device__ __nv_bfloat16 g_vtok[(size_t)NB * NV * NE];       // 19.4 MB
__device__ __nv_bfloat16 g_ttok[(size_t)NQ * NT * NE];       //  7.6 MB

__device__ __forceinline__ uint32_t smem_u32(const void* p) {
    uint32_t a;
    asm("{ .reg .u64 t; cvta.to.shared.u64 t, %1; cvt.u32.u64 %0, t; }"
        : "=r"(a) : "l"(p));
    return a;
}
__device__ __forceinline__ void ldmatrix_x4(uint32_t* r, uint32_t addr) {
    asm volatile("ldmatrix.sync.aligned.m8n8.x4.shared.b16 {%0,%1,%2,%3}, [%4];"
        : "=r"(r[0]), "=r"(r[1]), "=r"(r[2]), "=r"(r[3]) : "r"(addr));
}
__device__ __forceinline__ void ldmatrix_x2(uint32_t* r, uint32_t addr) {
    asm volatile("ldmatrix.sync.aligned.m8n8.x2.shared.b16 {%0,%1}, [%2];"
        : "=r"(r[0]), "=r"(r[1]) : "r"(addr));
}
__device__ __forceinline__ void mma_16816(float* c, const uint32_t* a, const uint32_t* b) {
    asm volatile("mma.sync.aligned.m16n8k16.row.col.f32.bf16.bf16.f32 "
        "{%0,%1,%2,%3}, {%4,%5,%6,%7}, {%8,%9}, {%0,%1,%2,%3};"
        : "+f"(c[0]), "+f"(c[1]), "+f"(c[2]), "+f"(c[3])
        : "r"(a[0]), "r"(a[1]), "r"(a[2]), "r"(a[3]), "r"(b[0]), "r"(b[1]));
}

// ===========================================================================
// Projection GEMM (fp32): Y[r,e] = sum_d X[r,d]*W[e,d] + bias[e]
// ===========================================================================
__global__ __launch_bounds__(256) void proj_gemm(
    const float* __restrict__ X, const float* __restrict__ W,
    const float* __restrict__ bias, float* __restrict__ Y, int R)
{
    __shared__ float As[16][68];
    __shared__ float Bs[16][68];
    const int r0 = blockIdx.x * 64, e0 = blockIdx.y * 64;
    const int tid = threadIdx.x;
    const int ty = tid >> 4, tx = tid & 15;
    const int lrow = tid >> 2, lk4 = tid & 3;

    float acc[4][4];
#pragma unroll
    for (int i = 0; i < 4; i++)
#pragma unroll
        for (int j = 0; j < 4; j++) acc[i][j] = 0.f;

    const int r_ld = r0 + lrow;
    const float4 zero4 = make_float4(0.f, 0.f, 0.f, 0.f);

    for (int k0 = 0; k0 < ND; k0 += 16) {
        float4 av = (r_ld < R)
            ? *(const float4*)(X + (size_t)r_ld * ND + k0 + lk4 * 4) : zero4;
        float4 bv = *(const float4*)(W + (size_t)(e0 + lrow) * ND + k0 + lk4 * 4);
        __syncthreads();
        As[lk4 * 4 + 0][lrow] = av.x; As[lk4 * 4 + 1][lrow] = av.y;
        As[lk4 * 4 + 2][lrow] = av.z; As[lk4 * 4 + 3][lrow] = av.w;
        Bs[lk4 * 4 + 0][lrow] = bv.x; Bs[lk4 * 4 + 1][lrow] = bv.y;
        Bs[lk4 * 4 + 2][lrow] = bv.z; Bs[lk4 * 4 + 3][lrow] = bv.w;
        __syncthreads();
#pragma unroll
        for (int kk = 0; kk < 16; kk++) {
            float4 a = *(const float4*)&As[kk][ty * 4];
            float4 b = *(const float4*)&Bs[kk][tx * 4];
            float aa[4] = {a.x, a.y, a.z, a.w};
            float bb[4] = {b.x, b.y, b.z, b.w};
#pragma unroll
            for (int i = 0; i < 4; i++)
#pragma unroll
                for (int j = 0; j < 4; j++)
                    acc[i][j] = fmaf(aa[i], bb[j], acc[i][j]);
        }
    }
#pragma unroll
    for (int i = 0; i < 4; i++) {
        int r = r0 + ty * 4 + i;
        if (r < R) {
#pragma unroll
            for (int j = 0; j < 4; j++) {
                int e = e0 + tx * 4 + j;
                Y[(size_t)r * NE + e] = acc[i][j] + bias[e];
            }
        }
    }
}

// ===========================================================================
// L2-normalize rows (fp32 in), write bf16 operand buffers
// ===========================================================================
__global__ __launch_bounds__(256) void l2norm_rows()
{
    const int NROWS_V = NB * NV;
    const int NROWS = NROWS_V + NQ * NT;
    int row = blockIdx.x * 8 + (threadIdx.x >> 5);
    int lane = threadIdx.x & 31;
    if (row >= NROWS) return;
    const float* src;
    __nv_bfloat16* dst;
    if (row < NROWS_V) {
        src = g_vtok_f32 + (size_t)row * NE;
        dst = g_vtok + (size_t)row * NE;
    } else {
        src = g_ttok_f32 + (size_t)(row - NROWS_V) * NE;
        dst = g_ttok + (size_t)(row - NROWS_V) * NE;
    }
    const float4* p4 = (const float4*)src;
    float s = 0.f;
#pragma unroll
    for (int i = lane; i < NE / 4; i += 32) {
        float4 v = p4[i];
        s += v.x * v.x + v.y * v.y + v.z * v.z + v.w * v.w;
    }
#pragma unroll
    for (int off = 16; off > 0; off >>= 1)
        s += __shfl_xor_sync(0xffffffffu, s, off);
    float inv = 1.f / fmaxf(sqrtf(s), 1e-12f);
    __nv_bfloat162* d2 = (__nv_bfloat162*)dst;
#pragma unroll
    for (int i = lane; i < NE / 4; i += 32) {
        float4 v = p4[i];
        d2[2 * i]     = __float22bfloat162_rn(make_float2(v.x * inv, v.y * inv));
        d2[2 * i + 1] = __float22bfloat162_rn(make_float2(v.z * inv, v.w * inv));
    }
}

// ===========================================================================
// Stage 2: mma.sync bf16 GEMM per (b,q) + fused masked max/sum reductions
//   M=256 (197 padded), N=80 (77 padded), K=512 in 8x64 chunks.
//   512 threads / 16 warps; warp tile 32x40 (2 m-tiles x 5 n-tiles).
//   SMEM staging pitch 144B -> conflict-free ldmatrix.
// ===========================================================================
#define APITCH 144
#define BOFF   (256 * APITCH)                 // 36864
#define LWP    81
#define SMEM_DYN 63840                        // >= max(staging 48384, logits 63828)

__global__ __launch_bounds__(512, 1) void stage2(
    const int* __restrict__ text_length,
    float* __restrict__ t2v, float* __restrict__ v2t)
{
    extern __shared__ __align__(16) char dsm[];
    __shared__ float s_red[1024];

    const int tid = threadIdx.x;
    const int wid = tid >> 5, lane = tid & 31;
    const int q = blockIdx.x, b = blockIdx.y;

    const uint4* Va = (const uint4*)(g_vtok + (size_t)b * NV * NE);  // 64 u4/row
    const uint4* Tt = (const uint4*)(g_ttok + (size_t)q * NT * NE);

    const uint32_t smemA = smem_u32(dsm);
    const uint32_t smemB = smemA + BOFF;

    const int mrow = (wid & 7) * 32;
    const int ncol = (wid >> 3) * 40;
    const uint32_t aaddr = smemA
        + (uint32_t)(mrow + (lane & 7) + ((lane >> 3) & 1) * 8) * APITCH
        + (uint32_t)(lane >> 4) * 16;
    const uint32_t baddr = smemB
        + (uint32_t)(ncol + (lane & 7)) * APITCH
        + (uint32_t)((lane >> 3) & 1) * 16;

    float c[2][5][4];
#pragma unroll
    for (int mi = 0; mi < 2; mi++)
#pragma unroll
        for (int ni = 0; ni < 5; ni++)
#pragma unroll
            for (int j = 0; j < 4; j++) c[mi][ni][j] = 0.f;

    const uint4 z4 = make_uint4(0, 0, 0, 0);
    uint4 ra[4], rb[2];

    // preload chunk 0
#pragma unroll
    for (int it = 0; it < 4; it++) {
        int slot = it * 512 + tid, row = slot >> 3, seg = slot & 7;
        ra[it] = (row < NV) ? Va[row * 64 + seg] : z4;
    }
#pragma unroll
    for (int it = 0; it < 2; it++) {
        int slot = it * 512 + tid;
        rb[it] = z4;
        if (slot < 640) {
            int row = slot >> 3, seg = slot & 7;
            if (row < NT) rb[it] = Tt[row * 64 + seg];
        }
    }

    for (int ch = 0; ch < 8; ch++) {
        __syncthreads();                       // previous MMA reads complete
#pragma unroll
        for (int it = 0; it < 4; it++) {
            int slot = it * 512 + tid, row = slot >> 3, seg = slot & 7;
            *(uint4*)(dsm + row * APITCH + seg * 16) = ra[it];
        }
#pragma unroll
        for (int it = 0; it < 2; it++) {
            int slot = it * 512 + tid;
            if (slot < 640) {
                int row = slot >> 3, seg = slot & 7;
                *(uint4*)(dsm + BOFF + row * APITCH + seg * 16) = rb[it];
            }
        }
        __syncthreads();

        if (ch < 7) {                          // prefetch overlaps MMA
            int kf4 = (ch + 1) * 8;
#pragma unroll
            for (int it = 0; it < 4; it++) {
                int slot = it * 512 + tid, row = slot >> 3, seg = slot & 7;
                ra[it] = (row < NV) ? Va[row * 64 + kf4 + seg] : z4;
            }
#pragma unroll
            for (int it = 0; it < 2; it++) {
                int slot = it * 512 + tid;
                rb[it] = z4;
                if (slot < 640) {
                    int row = slot >> 3, seg = slot & 7;
                    if (row < NT) rb[it] = Tt[row * 64 + kf4 + seg];
                }
            }
        }

#pragma unroll
        for (int ks = 0; ks < 4; ks++) {
            uint32_t af[2][4], bf[5][2];
#pragma unroll
            for (int mi = 0; mi < 2; mi++)
                ldmatrix_x4(af[mi], aaddr + mi * (16 * APITCH) + ks * 32);
#pragma unroll
            for (int ni = 0; ni < 5; ni++)
                ldmatrix_x2(bf[ni], baddr + ni * (8 * APITCH) + ks * 32);
#pragma unroll
            for (int mi = 0; mi < 2; mi++)
#pragma unroll
                for (int ni = 0; ni < 5; ni++)
                    mma_16816(c[mi][ni], af[mi], bf[ni]);
        }
    }
    __syncthreads();

    // ---- epilogue: spill frags to SMEM logits, then masked reductions ----
    float* logits = (float*)dsm;               // 197 x LWP
#pragma unroll
    for (int mi = 0; mi < 2; mi++) {
#pragma unroll
        for (int ni = 0; ni < 5; ni++) {
            int r0 = mrow + mi * 16 + (lane >> 2);
            int cc = ncol + ni * 8 + ((lane & 3) << 1);
            float* cf = c[mi][ni];
            if (cc < NT) {
                if (r0 < NV)     logits[r0 * LWP + cc] = cf[0];
                if (r0 + 8 < NV) logits[(r0 + 8) * LWP + cc] = cf[2];
            }
            if (cc + 1 < NT) {
                if (r0 < NV)     logits[r0 * LWP + cc + 1] = cf[1];
                if (r0 + 8 < NV) logits[(r0 + 8) * LWP + cc + 1] = cf[3];
            }
        }
    }
    __syncthreads();

    const int len = text_length[q];
    float p_t2v = 0.f, p_v2t = 0.f;

    // t2v: per valid text token t<len, max over 197 v
    if (tid < NT) {
        float cm = -INFINITY;
        for (int v = 0; v < NV; v++) cm = fmaxf(cm, logits[v * LWP + tid]);
        if (tid < len) p_t2v = cm;
    }
    // v2t: per v, max over t of masked logit (t>=len contributes 0.0)
    for (int v = tid; v < NV; v += 512) {
        float m = -INFINITY;
        for (int t = 0; t < NT; t++) {
            float val = (t < len) ? logits[v * LWP + t] : 0.f;
            m = fmaxf(m, val);
        }
        p_v2t += m;
    }
    s_red[tid] = p_t2v;
    s_red[512 + tid] = p_v2t;
    __syncthreads();
#pragma unroll
    for (int s = 256; s > 0; s >>= 1) {
        if (tid < s) {
            s_red[tid] += s_red[tid + s];
            s_red[512 + tid] += s_red[512 + tid + s];
        }
        __syncthreads();
    }
    if (tid == 0) {
        t2v[b * NQ + q] = s_red[0] / (float)len;
        v2t[b * NQ + q] = s_red[512] / (float)NV;
    }
}

// ===========================================================================
extern "C" void kernel_launch(void* const* d_in, const int* in_sizes, int n_in,
                              void* d_out, int out_size)
{
    const float* visual_cls     = (const float*)d_in[0];
    const float* visual_tokens  = (const float*)d_in[1];
    const float* textual_cls    = (const float*)d_in[2];
    const float* textual_tokens = (const float*)d_in[3];
    const float* Wv_cls = (const float*)d_in[4];
    const float* bv_cls = (const float*)d_in[5];
    const float* Wt_cls = (const float*)d_in[6];
    const float* bt_cls = (const float*)d_in[7];
    const float* Wv_tok = (const float*)d_in[8];
    const float* bv_tok = (const float*)d_in[9];
    const float* Wt_tok = (const float*)d_in[10];
    const float* bt_tok = (const float*)d_in[11];
    const int*   text_length = (const int*)d_in[12];

    float* out = (float*)d_out;
    float* o_vcls = out;
    float* o_tcls = out + NB * NE;
    float* o_t2v  = out + 2 * NB * NE;
    float* o_v2t  = o_t2v + NB * NQ;

    float *pv, *pt;
    cudaGetSymbolAddress((void**)&pv, g_vtok_f32);
    cudaGetSymbolAddress((void**)&pt, g_ttok_f32);

    // Stage 1: fp32 projections
    proj_gemm<<<dim3(2, 8), 256>>>(visual_cls, Wv_cls, bv_cls, o_vcls, NB);
    proj_gemm<<<dim3(2, 8), 256>>>(textual_cls, Wt_cls, bt_cls, o_tcls, NQ);
    proj_gemm<<<dim3((NB * NV + 63) / 64, 8), 256>>>(visual_tokens, Wv_tok, bv_tok, pv, NB * NV);
    proj_gemm<<<dim3((NQ * NT + 63) / 64, 8), 256>>>(textual_tokens, Wt_tok, bt_tok, pt, NQ * NT);

    // Stage 1b: normalize + bf16 convert
    l2norm_rows<<<(NB * NV + NQ * NT + 7) / 8, 256>>>();

    // Stage 2: mma.sync bf16 similarity + fused reductions
    cudaFuncSetAttribute(stage2, cudaFuncAttributeMaxDynamicSharedMemorySize, SMEM_DYN);
    stage2<<<dim3(NQ, NB), 512, SMEM_DYN>>>(text_length, o_t2v, o_v2t);
}

// round 5
// speedup vs baseline: 4.9894x; 1.4649x over previous
#include <cuda_runtime.h>
#include <cuda_bf16.h>
#include <math.h>
#include <stdint.h>

// Problem dims (fixed)
#define NB 96
#define NQ 96
#define NV 197
#define NT 77
#define ND 768
#define NE 512

// Scratch: fp32 projection outputs, then bf16 normalized operands (L2-resident)
__device__ float         g_vtok_f32[(size_t)NB * NV * NE];   // 38.7 MB
__device__ float         g_ttok_f32[(size_t)NQ * NT * NE];   // 15.1 MB
__device__ __nv_bfloat16 g_vtok[(size_t)NB * NV * NE];       // 19.4 MB
__device__ __nv_bfloat16 g_ttok[(size_t)NQ * NT * NE];       //  7.6 MB

__device__ __forceinline__ uint32_t smem_u32(const void* p) {
    uint32_t a;
    asm("{ .reg .u64 t; cvta.to.shared.u64 t, %1; cvt.u32.u64 %0, t; }"
        : "=r"(a) : "l"(p));
    return a;
}
__device__ __forceinline__ void ldmatrix_x4(uint32_t* r, uint32_t addr) {
    asm volatile("ldmatrix.sync.aligned.m8n8.x4.shared.b16 {%0,%1,%2,%3}, [%4];"
        : "=r"(r[0]), "=r"(r[1]), "=r"(r[2]), "=r"(r[3]) : "r"(addr));
}
__device__ __forceinline__ void ldmatrix_x2(uint32_t* r, uint32_t addr) {
    asm volatile("ldmatrix.sync.aligned.m8n8.x2.shared.b16 {%0,%1}, [%2];"
        : "=r"(r[0]), "=r"(r[1]) : "r"(addr));
}
__device__ __forceinline__ void mma_16816(float* c, const uint32_t* a, const uint32_t* b) {
    asm volatile("mma.sync.aligned.m16n8k16.row.col.f32.bf16.bf16.f32 "
        "{%0,%1,%2,%3}, {%4,%5,%6,%7}, {%8,%9}, {%0,%1,%2,%3};"
        : "+f"(c[0]), "+f"(c[1]), "+f"(c[2]), "+f"(c[3])
        : "r"(a[0]), "r"(a[1]), "r"(a[2]), "r"(a[3]), "r"(b[0]), "r"(b[1]));
}
__device__ __forceinline__ uint4 f32x8_bf16(float4 a, float4 b) {
    uint4 r;
    __nv_bfloat162 p;
    p = __float22bfloat162_rn(make_float2(a.x, a.y)); r.x = *(uint32_t*)&p;
    p = __float22bfloat162_rn(make_float2(a.z, a.w)); r.y = *(uint32_t*)&p;
    p = __float22bfloat162_rn(make_float2(b.x, b.y)); r.z = *(uint32_t*)&p;
    p = __float22bfloat162_rn(make_float2(b.z, b.w)); r.w = *(uint32_t*)&p;
    return r;
}

// ===========================================================================
// cls projection GEMM (exact fp32 SIMT — cls outputs dominate output norm)
// ===========================================================================
__global__ __launch_bounds__(256) void proj_gemm(
    const float* __restrict__ X, const float* __restrict__ W,
    const float* __restrict__ bias, float* __restrict__ Y, int R)
{
    __shared__ float As[16][68];
    __shared__ float Bs[16][68];
    const int r0 = blockIdx.x * 64, e0 = blockIdx.y * 64;
    const int tid = threadIdx.x;
    const int ty = tid >> 4, tx = tid & 15;
    const int lrow = tid >> 2, lk4 = tid & 3;

    float acc[4][4];
#pragma unroll
    for (int i = 0; i < 4; i++)
#pragma unroll
        for (int j = 0; j < 4; j++) acc[i][j] = 0.f;

    const int r_ld = r0 + lrow;
    const float4 zero4 = make_float4(0.f, 0.f, 0.f, 0.f);

    for (int k0 = 0; k0 < ND; k0 += 16) {
        float4 av = (r_ld < R)
            ? *(const float4*)(X + (size_t)r_ld * ND + k0 + lk4 * 4) : zero4;
        float4 bv = *(const float4*)(W + (size_t)(e0 + lrow) * ND + k0 + lk4 * 4);
        __syncthreads();
        As[lk4 * 4 + 0][lrow] = av.x; As[lk4 * 4 + 1][lrow] = av.y;
        As[lk4 * 4 + 2][lrow] = av.z; As[lk4 * 4 + 3][lrow] = av.w;
        Bs[lk4 * 4 + 0][lrow] = bv.x; Bs[lk4 * 4 + 1][lrow] = bv.y;
        Bs[lk4 * 4 + 2][lrow] = bv.z; Bs[lk4 * 4 + 3][lrow] = bv.w;
        __syncthreads();
#pragma unroll
        for (int kk = 0; kk < 16; kk++) {
            float4 a = *(const float4*)&As[kk][ty * 4];
            float4 b = *(const float4*)&Bs[kk][tx * 4];
            float aa[4] = {a.x, a.y, a.z, a.w};
            float bb[4] = {b.x, b.y, b.z, b.w};
#pragma unroll
            for (int i = 0; i < 4; i++)
#pragma unroll
                for (int j = 0; j < 4; j++)
                    acc[i][j] = fmaf(aa[i], bb[j], acc[i][j]);
        }
    }
#pragma unroll
    for (int i = 0; i < 4; i++) {
        int r = r0 + ty * 4 + i;
        if (r < R) {
#pragma unroll
            for (int j = 0; j < 4; j++) {
                int e = e0 + tx * 4 + j;
                Y[(size_t)r * NE + e] = acc[i][j] + bias[e];
            }
        }
    }
}

// ===========================================================================
// Token projection via mma.sync bf16: Y[r,e] = sum_d X[r,d]*W[e,d] + bias[e]
//   BM=128, BN=128, BK=64; 256 thr / 8 warps; warp tile 32x64.
//   fp32 gmem loads converted to bf16 in-register, staged pitch-144.
// ===========================================================================
#define PPITCH 144

__global__ __launch_bounds__(256) void proj_mma(
    const float* __restrict__ X, const float* __restrict__ W,
    const float* __restrict__ bias, float* __restrict__ Y, int R)
{
    __shared__ __align__(16) char sm[2 * 128 * PPITCH];   // 36864 B
    char* smA = sm;
    char* smB = sm + 128 * PPITCH;
    const int tid = threadIdx.x, wid = tid >> 5, lane = tid & 31;
    const int r0 = blockIdx.x * 128, e0 = blockIdx.y * 128;
    const int mrow = (wid & 3) * 32, ncol = (wid >> 2) * 64;

    const uint32_t aaddr = smem_u32(smA)
        + (uint32_t)(mrow + (lane & 7) + ((lane >> 3) & 1) * 8) * PPITCH
        + (uint32_t)(lane >> 4) * 16;
    const uint32_t baddr = smem_u32(smB)
        + (uint32_t)(ncol + (lane & 7)) * PPITCH
        + (uint32_t)((lane >> 3) & 1) * 16;

    float c[2][8][4];
#pragma unroll
    for (int mi = 0; mi < 2; mi++)
#pragma unroll
        for (int ni = 0; ni < 8; ni++)
#pragma unroll
            for (int j = 0; j < 4; j++) c[mi][ni][j] = 0.f;

    const int row = tid >> 3, seg = tid & 7;   // per-thread fixed (row, 8-elem seg)
    uint4 pa[4], pb[4];

    // preload chunk 0 (k0 = 0), converting fp32 -> bf16
#pragma unroll
    for (int it = 0; it < 4; it++) {
        int rr = r0 + it * 32 + row;
        if (rr < R) {
            const float4* p = (const float4*)(X + (size_t)rr * ND + seg * 8);
            pa[it] = f32x8_bf16(p[0], p[1]);
        } else pa[it] = make_uint4(0, 0, 0, 0);
        const float4* pw = (const float4*)(W + (size_t)(e0 + it * 32 + row) * ND + seg * 8);
        pb[it] = f32x8_bf16(pw[0], pw[1]);
    }

    for (int ch = 0; ch < 12; ch++) {
        __syncthreads();
#pragma unroll
        for (int it = 0; it < 4; it++) {
            *(uint4*)(smA + (it * 32 + row) * PPITCH + seg * 16) = pa[it];
            *(uint4*)(smB + (it * 32 + row) * PPITCH + seg * 16) = pb[it];
        }
        __syncthreads();

        if (ch < 11) {                         // prefetch next chunk
            int k0 = (ch + 1) * 64;
#pragma unroll
            for (int it = 0; it < 4; it++) {
                int rr = r0 + it * 32 + row;
                if (rr < R) {
                    const float4* p = (const float4*)(X + (size_t)rr * ND + k0 + seg * 8);
                    pa[it] = f32x8_bf16(p[0], p[1]);
                } else pa[it] = make_uint4(0, 0, 0, 0);
                const float4* pw = (const float4*)(W + (size_t)(e0 + it * 32 + row) * ND + k0 + seg * 8);
                pb[it] = f32x8_bf16(pw[0], pw[1]);
            }
        }

#pragma unroll
        for (int ks = 0; ks < 4; ks++) {
            uint32_t af[2][4], bf[8][2];
#pragma unroll
            for (int mi = 0; mi < 2; mi++)
                ldmatrix_x4(af[mi], aaddr + mi * (16 * PPITCH) + ks * 32);
#pragma unroll
            for (int ni = 0; ni < 8; ni++)
                ldmatrix_x2(bf[ni], baddr + ni * (8 * PPITCH) + ks * 32);
#pragma unroll
            for (int mi = 0; mi < 2; mi++)
#pragma unroll
                for (int ni = 0; ni < 8; ni++)
                    mma_16816(c[mi][ni], af[mi], bf[ni]);
        }
    }

    // epilogue: add bias, store fp32
#pragma unroll
    for (int mi = 0; mi < 2; mi++) {
        int rr = r0 + mrow + mi * 16 + (lane >> 2);
        if (rr < R) {
#pragma unroll
            for (int ni = 0; ni < 8; ni++) {
                int e = e0 + ncol + ni * 8 + ((lane & 3) << 1);
                float2 o;
                o.x = c[mi][ni][0] + bias[e];
                o.y = c[mi][ni][1] + bias[e + 1];
                *(float2*)(Y + (size_t)rr * NE + e) = o;
                o.x = c[mi][ni][2] + bias[e];
                o.y = c[mi][ni][3] + bias[e + 1];
                *(float2*)(Y + (size_t)(rr + 8) * NE + e) = o;
            }
        }
    }
}

// ===========================================================================
// L2-normalize rows (fp32 in), write bf16 operand buffers
// ===========================================================================
__global__ __launch_bounds__(256) void l2norm_rows()
{
    const int NROWS_V = NB * NV;
    const int NROWS = NROWS_V + NQ * NT;
    int row = blockIdx.x * 8 + (threadIdx.x >> 5);
    int lane = threadIdx.x & 31;
    if (row >= NROWS) return;
    const float* src;
    __nv_bfloat16* dst;
    if (row < NROWS_V) {
        src = g_vtok_f32 + (size_t)row * NE;
        dst = g_vtok + (size_t)row * NE;
    } else {
        src = g_ttok_f32 + (size_t)(row - NROWS_V) * NE;
        dst = g_ttok + (size_t)(row - NROWS_V) * NE;
    }
    const float4* p4 = (const float4*)src;
    float s = 0.f;
#pragma unroll
    for (int i = lane; i < NE / 4; i += 32) {
        float4 v = p4[i];
        s += v.x * v.x + v.y * v.y + v.z * v.z + v.w * v.w;
    }
#pragma unroll
    for (int off = 16; off > 0; off >>= 1)
        s += __shfl_xor_sync(0xffffffffu, s, off);
    float inv = 1.f / fmaxf(sqrtf(s), 1e-12f);
    __nv_bfloat162* d2 = (__nv_bfloat162*)dst;
#pragma unroll
    for (int i = lane; i < NE / 4; i += 32) {
        float4 v = p4[i];
        d2[2 * i]     = __float22bfloat162_rn(make_float2(v.x * inv, v.y * inv));
        d2[2 * i + 1] = __float22bfloat162_rn(make_float2(v.z * inv, v.w * inv));
    }
}

// ===========================================================================
// Stage 2: mma.sync bf16 GEMM per (b,q) + fused masked max/sum reductions
// ===========================================================================
#define APITCH 144
#define BOFF   (256 * APITCH)
#define LWP    81
#define SMEM_DYN 63840

__global__ __launch_bounds__(512, 1) void stage2(
    const int* __restrict__ text_length,
    float* __restrict__ t2v, float* __restrict__ v2t)
{
    extern __shared__ __align__(16) char dsm[];
    __shared__ float s_red[1024];

    const int tid = threadIdx.x;
    const int wid = tid >> 5, lane = tid & 31;
    const int q = blockIdx.x, b = blockIdx.y;

    const uint4* Va = (const uint4*)(g_vtok + (size_t)b * NV * NE);
    const uint4* Tt = (const uint4*)(g_ttok + (size_t)q * NT * NE);

    const uint32_t smemA = smem_u32(dsm);
    const uint32_t smemB = smemA + BOFF;

    const int mrow = (wid & 7) * 32;
    const int ncol = (wid >> 3) * 40;
    const uint32_t aaddr = smemA
        + (uint32_t)(mrow + (lane & 7) + ((lane >> 3) & 1) * 8) * APITCH
        + (uint32_t)(lane >> 4) * 16;
    const uint32_t baddr = smemB
        + (uint32_t)(ncol + (lane & 7)) * APITCH
        + (uint32_t)((lane >> 3) & 1) * 16;

    float c[2][5][4];
#pragma unroll
    for (int mi = 0; mi < 2; mi++)
#pragma unroll
        for (int ni = 0; ni < 5; ni++)
#pragma unroll
            for (int j = 0; j < 4; j++) c[mi][ni][j] = 0.f;

    const uint4 z4 = make_uint4(0, 0, 0, 0);
    uint4 ra[4], rb[2];

#pragma unroll
    for (int it = 0; it < 4; it++) {
        int slot = it * 512 + tid, row = slot >> 3, seg = slot & 7;
        ra[it] = (row < NV) ? Va[row * 64 + seg] : z4;
    }
#pragma unroll
    for (int it = 0; it < 2; it++) {
        int slot = it * 512 + tid;
        rb[it] = z4;
        if (slot < 640) {
            int row = slot >> 3, seg = slot & 7;
            if (row < NT) rb[it] = Tt[row * 64 + seg];
        }
    }

    for (int ch = 0; ch < 8; ch++) {
        __syncthreads();
#pragma unroll
        for (int it = 0; it < 4; it++) {
            int slot = it * 512 + tid, row = slot >> 3, seg = slot & 7;
            *(uint4*)(dsm + row * APITCH + seg * 16) = ra[it];
        }
#pragma unroll
        for (int it = 0; it < 2; it++) {
            int slot = it * 512 + tid;
            if (slot < 640) {
                int row = slot >> 3, seg = slot & 7;
                *(uint4*)(dsm + BOFF + row * APITCH + seg * 16) = rb[it];
            }
        }
        __syncthreads();

        if (ch < 7) {
            int kf4 = (ch + 1) * 8;
#pragma unroll
            for (int it = 0; it < 4; it++) {
                int slot = it * 512 + tid, row = slot >> 3, seg = slot & 7;
                ra[it] = (row < NV) ? Va[row * 64 + kf4 + seg] : z4;
            }
#pragma unroll
            for (int it = 0; it < 2; it++) {
                int slot = it * 512 + tid;
                rb[it] = z4;
                if (slot < 640) {
                    int row = slot >> 3, seg = slot & 7;
                    if (row < NT) rb[it] = Tt[row * 64 + kf4 + seg];
                }
            }
        }

#pragma unroll
        for (int ks = 0; ks < 4; ks++) {
            uint32_t af[2][4], bf[5][2];
#pragma unroll
            for (int mi = 0; mi < 2; mi++)
                ldmatrix_x4(af[mi], aaddr + mi * (16 * APITCH) + ks * 32);
#pragma unroll
            for (int ni = 0; ni < 5; ni++)
                ldmatrix_x2(bf[ni], baddr + ni * (8 * APITCH) + ks * 32);
#pragma unroll
            for (int mi = 0; mi < 2; mi++)
#pragma unroll
                for (int ni = 0; ni < 5; ni++)
                    mma_16816(c[mi][ni], af[mi], bf[ni]);
        }
    }
    __syncthreads();

    float* logits = (float*)dsm;
#pragma unroll
    for (int mi = 0; mi < 2; mi++) {
#pragma unroll
        for (int ni = 0; ni < 5; ni++) {
            int r0 = mrow + mi * 16 + (lane >> 2);
            int cc = ncol + ni * 8 + ((lane & 3) << 1);
            float* cf = c[mi][ni];
            if (cc < NT) {
                if (r0 < NV)     logits[r0 * LWP + cc] = cf[0];
                if (r0 + 8 < NV) logits[(r0 + 8) * LWP + cc] = cf[2];
            }
            if (cc + 1 < NT) {
                if (r0 < NV)     logits[r0 * LWP + cc + 1] = cf[1];
                if (r0 + 8 < NV) logits[(r0 + 8) * LWP + cc + 1] = cf[3];
            }
        }
    }
    __syncthreads();

    const int len = text_length[q];
    float p_t2v = 0.f, p_v2t = 0.f;

    if (tid < NT) {
        float cm = -INFINITY;
        for (int v = 0; v < NV; v++) cm = fmaxf(cm, logits[v * LWP + tid]);
        if (tid < len) p_t2v = cm;
    }
    for (int v = tid; v < NV; v += 512) {
        float m = -INFINITY;
        for (int t = 0; t < NT; t++) {
            float val = (t < len) ? logits[v * LWP + t] : 0.f;
            m = fmaxf(m, val);
        }
        p_v2t += m;
    }
    s_red[tid] = p_t2v;
    s_red[512 + tid] = p_v2t;
    __syncthreads();
#pragma unroll
    for (int s = 256; s > 0; s >>= 1) {
        if (tid < s) {
            s_red[tid] += s_red[tid + s];
            s_red[512 + tid] += s_red[512 + tid + s];
        }
        __syncthreads();
    }
    if (tid == 0) {
        t2v[b * NQ + q] = s_red[0] / (float)len;
        v2t[b * NQ + q] = s_red[512] / (float)NV;
    }
}

// ===========================================================================
extern "C" void kernel_launch(void* const* d_in, const int* in_sizes, int n_in,
                              void* d_out, int out_size)
{
    const float* visual_cls     = (const float*)d_in[0];
    const float* visual_tokens  = (const float*)d_in[1];
    const float* textual_cls    = (const float*)d_in[2];
    const float* textual_tokens = (const float*)d_in[3];
    const float* Wv_cls = (const float*)d_in[4];
    const float* bv_cls = (const float*)d_in[5];
    const float* Wt_cls = (const float*)d_in[6];
    const float* bt_cls = (const float*)d_in[7];
    const float* Wv_tok = (const float*)d_in[8];
    const float* bv_tok = (const float*)d_in[9];
    const float* Wt_tok = (const float*)d_in[10];
    const float* bt_tok = (const float*)d_in[11];
    const int*   text_length = (const int*)d_in[12];

    float* out = (float*)d_out;
    float* o_vcls = out;
    float* o_tcls = out + NB * NE;
    float* o_t2v  = out + 2 * NB * NE;
    float* o_v2t  = o_t2v + NB * NQ;

    float *pv, *pt;
    cudaGetSymbolAddress((void**)&pv, g_vtok_f32);
    cudaGetSymbolAddress((void**)&pt, g_ttok_f32);

    // cls projections: exact fp32
    proj_gemm<<<dim3(2, 8), 256>>>(visual_cls, Wv_cls, bv_cls, o_vcls, NB);
    proj_gemm<<<dim3(2, 8), 256>>>(textual_cls, Wt_cls, bt_cls, o_tcls, NQ);

    // token projections: bf16 mma.sync
    proj_mma<<<dim3((NB * NV + 127) / 128, 4), 256>>>(visual_tokens, Wv_tok, bv_tok, pv, NB * NV);
    proj_mma<<<dim3((NQ * NT + 127) / 128, 4), 256>>>(textual_tokens, Wt_tok, bt_tok, pt, NQ * NT);

    // normalize + bf16 convert
    l2norm_rows<<<(NB * NV + NQ * NT + 7) / 8, 256>>>();

    // similarity + fused reductions
    cudaFuncSetAttribute(stage2, cudaFuncAttributeMaxDynamicSharedMemorySize, SMEM_DYN);
    stage2<<<dim3(NQ, NB), 512, SMEM_DYN>>>(text_length, o_t2v, o_v2t);
}

// round 6
// speedup vs baseline: 5.8842x; 1.1793x over previous
#include <cuda_runtime.h>
#include <cuda_bf16.h>
#include <math.h>
#include <stdint.h>

// Problem dims (fixed)
#define NB 96
#define NQ 96
#define NV 197
#define NT 77
#define ND 768
#define NE 512

__device__ float         g_vtok_f32[(size_t)NB * NV * NE];
__device__ float         g_ttok_f32[(size_t)NQ * NT * NE];
__device__ __nv_bfloat16 g_vtok[(size_t)NB * NV * NE];
__device__ __nv_bfloat16 g_ttok[(size_t)NQ * NT * NE];

__device__ __forceinline__ uint32_t smem_u32(const void* p) {
    uint32_t a;
    asm("{ .reg .u64 t; cvta.to.shared.u64 t, %1; cvt.u32.u64 %0, t; }"
        : "=r"(a) : "l"(p));
    return a;
}
__device__ __forceinline__ void ldmatrix_x4(uint32_t* r, uint32_t addr) {
    asm volatile("ldmatrix.sync.aligned.m8n8.x4.shared.b16 {%0,%1,%2,%3}, [%4];"
        : "=r"(r[0]), "=r"(r[1]), "=r"(r[2]), "=r"(r[3]) : "r"(addr));
}
__device__ __forceinline__ void ldmatrix_x2(uint32_t* r, uint32_t addr) {
    asm volatile("ldmatrix.sync.aligned.m8n8.x2.shared.b16 {%0,%1}, [%2];"
        : "=r"(r[0]), "=r"(r[1]) : "r"(addr));
}
__device__ __forceinline__ void mma_16816(float* c, const uint32_t* a, const uint32_t* b) {
    asm volatile("mma.sync.aligned.m16n8k16.row.col.f32.bf16.bf16.f32 "
        "{%0,%1,%2,%3}, {%4,%5,%6,%7}, {%8,%9}, {%0,%1,%2,%3};"
        : "+f"(c[0]), "+f"(c[1]), "+f"(c[2]), "+f"(c[3])
        : "r"(a[0]), "r"(a[1]), "r"(a[2]), "r"(a[3]), "r"(b[0]), "r"(b[1]));
}
__device__ __forceinline__ void cp16(uint32_t dst, const void* src, bool pred) {
    int sz = pred ? 16 : 0;
    asm volatile("cp.async.cg.shared.global [%0], [%1], 16, %2;"
        :: "r"(dst), "l"(src), "r"(sz) : "memory");
}
#define CP_COMMIT() asm volatile("cp.async.commit_group;" ::: "memory")
__device__ __forceinline__ uint4 f32x8_bf16(float4 a, float4 b) {
    uint4 r;
    __nv_bfloat162 p;
    p = __float22bfloat162_rn(make_float2(a.x, a.y)); r.x = *(uint32_t*)&p;
    p = __float22bfloat162_rn(make_float2(a.z, a.w)); r.y = *(uint32_t*)&p;
    p = __float22bfloat162_rn(make_float2(b.x, b.y)); r.z = *(uint32_t*)&p;
    p = __float22bfloat162_rn(make_float2(b.z, b.w)); r.w = *(uint32_t*)&p;
    return r;
}

// ===========================================================================
// cls projection GEMM (exact fp32 SIMT)
// ===========================================================================
__global__ __launch_bounds__(256) void proj_gemm(
    const float* __restrict__ X, const float* __restrict__ W,
    const float* __restrict__ bias, float* __restrict__ Y, int R)
{
    __shared__ float As[16][68];
    __shared__ float Bs[16][68];
    const int r0 = blockIdx.x * 64, e0 = blockIdx.y * 64;
    const int tid = threadIdx.x;
    const int ty = tid >> 4, tx = tid & 15;
    const int lrow = tid >> 2, lk4 = tid & 3;

    float acc[4][4];
#pragma unroll
    for (int i = 0; i < 4; i++)
#pragma unroll
        for (int j = 0; j < 4; j++) acc[i][j] = 0.f;

    const int r_ld = r0 + lrow;
    const float4 zero4 = make_float4(0.f, 0.f, 0.f, 0.f);

    for (int k0 = 0; k0 < ND; k0 += 16) {
        float4 av = (r_ld < R)
            ? *(const float4*)(X + (size_t)r_ld * ND + k0 + lk4 * 4) : zero4;
        float4 bv = *(const float4*)(W + (size_t)(e0 + lrow) * ND + k0 + lk4 * 4);
        __syncthreads();
        As[lk4 * 4 + 0][lrow] = av.x; As[lk4 * 4 + 1][lrow] = av.y;
        As[lk4 * 4 + 2][lrow] = av.z; As[lk4 * 4 + 3][lrow] = av.w;
        Bs[lk4 * 4 + 0][lrow] = bv.x; Bs[lk4 * 4 + 1][lrow] = bv.y;
        Bs[lk4 * 4 + 2][lrow] = bv.z; Bs[lk4 * 4 + 3][lrow] = bv.w;
        __syncthreads();
#pragma unroll
        for (int kk = 0; kk < 16; kk++) {
            float4 a = *(const float4*)&As[kk][ty * 4];
            float4 b = *(const float4*)&Bs[kk][tx * 4];
            float aa[4] = {a.x, a.y, a.z, a.w};
            float bb[4] = {b.x, b.y, b.z, b.w};
#pragma unroll
            for (int i = 0; i < 4; i++)
#pragma unroll
                for (int j = 0; j < 4; j++)
                    acc[i][j] = fmaf(aa[i], bb[j], acc[i][j]);
        }
    }
#pragma unroll
    for (int i = 0; i < 4; i++) {
        int r = r0 + ty * 4 + i;
        if (r < R) {
#pragma unroll
            for (int j = 0; j < 4; j++) {
                int e = e0 + tx * 4 + j;
                Y[(size_t)r * NE + e] = acc[i][j] + bias[e];
            }
        }
    }
}

// ===========================================================================
// Token projection via mma.sync bf16
// ===========================================================================
#define PPITCH 144

__global__ __launch_bounds__(256) void proj_mma(
    const float* __restrict__ X, const float* __restrict__ W,
    const float* __restrict__ bias, float* __restrict__ Y, int R)
{
    __shared__ __align__(16) char sm[2 * 128 * PPITCH];
    char* smA = sm;
    char* smB = sm + 128 * PPITCH;
    const int tid = threadIdx.x, wid = tid >> 5, lane = tid & 31;
    const int r0 = blockIdx.x * 128, e0 = blockIdx.y * 128;
    const int mrow = (wid & 3) * 32, ncol = (wid >> 2) * 64;

    const uint32_t aaddr = smem_u32(smA)
        + (uint32_t)(mrow + (lane & 7) + ((lane >> 3) & 1) * 8) * PPITCH
        + (uint32_t)(lane >> 4) * 16;
    const uint32_t baddr = smem_u32(smB)
        + (uint32_t)(ncol + (lane & 7)) * PPITCH
        + (uint32_t)((lane >> 3) & 1) * 16;

    float c[2][8][4];
#pragma unroll
    for (int mi = 0; mi < 2; mi++)
#pragma unroll
        for (int ni = 0; ni < 8; ni++)
#pragma unroll
            for (int j = 0; j < 4; j++) c[mi][ni][j] = 0.f;

    const int row = tid >> 3, seg = tid & 7;
    uint4 pa[4], pb[4];

#pragma unroll
    for (int it = 0; it < 4; it++) {
        int rr = r0 + it * 32 + row;
        if (rr < R) {
            const float4* p = (const float4*)(X + (size_t)rr * ND + seg * 8);
            pa[it] = f32x8_bf16(p[0], p[1]);
        } else pa[it] = make_uint4(0, 0, 0, 0);
        const float4* pw = (const float4*)(W + (size_t)(e0 + it * 32 + row) * ND + seg * 8);
        pb[it] = f32x8_bf16(pw[0], pw[1]);
    }

    for (int ch = 0; ch < 12; ch++) {
        __syncthreads();
#pragma unroll
        for (int it = 0; it < 4; it++) {
            *(uint4*)(smA + (it * 32 + row) * PPITCH + seg * 16) = pa[it];
            *(uint4*)(smB + (it * 32 + row) * PPITCH + seg * 16) = pb[it];
        }
        __syncthreads();

        if (ch < 11) {
            int k0 = (ch + 1) * 64;
#pragma unroll
            for (int it = 0; it < 4; it++) {
                int rr = r0 + it * 32 + row;
                if (rr < R) {
                    const float4* p = (const float4*)(X + (size_t)rr * ND + k0 + seg * 8);
                    pa[it] = f32x8_bf16(p[0], p[1]);
                } else pa[it] = make_uint4(0, 0, 0, 0);
                const float4* pw = (const float4*)(W + (size_t)(e0 + it * 32 + row) * ND + k0 + seg * 8);
                pb[it] = f32x8_bf16(pw[0], pw[1]);
            }
        }

#pragma unroll
        for (int ks = 0; ks < 4; ks++) {
            uint32_t af[2][4], bf[8][2];
#pragma unroll
            for (int mi = 0; mi < 2; mi++)
                ldmatrix_x4(af[mi], aaddr + mi * (16 * PPITCH) + ks * 32);
#pragma unroll
            for (int ni = 0; ni < 8; ni++)
                ldmatrix_x2(bf[ni], baddr + ni * (8 * PPITCH) + ks * 32);
#pragma unroll
            for (int mi = 0; mi < 2; mi++)
#pragma unroll
                for (int ni = 0; ni < 8; ni++)
                    mma_16816(c[mi][ni], af[mi], bf[ni]);
        }
    }

#pragma unroll
    for (int mi = 0; mi < 2; mi++) {
        int rr = r0 + mrow + mi * 16 + (lane >> 2);
        if (rr < R) {
#pragma unroll
            for (int ni = 0; ni < 8; ni++) {
                int e = e0 + ncol + ni * 8 + ((lane & 3) << 1);
                float2 o;
                o.x = c[mi][ni][0] + bias[e];
                o.y = c[mi][ni][1] + bias[e + 1];
                *(float2*)(Y + (size_t)rr * NE + e) = o;
                o.x = c[mi][ni][2] + bias[e];
                o.y = c[mi][ni][3] + bias[e + 1];
                *(float2*)(Y + (size_t)(rr + 8) * NE + e) = o;
            }
        }
    }
}

// ===========================================================================
// L2-normalize rows (fp32 in), write bf16 operand buffers
// ===========================================================================
__global__ __launch_bounds__(256) void l2norm_rows()
{
    const int NROWS_V = NB * NV;
    const int NROWS = NROWS_V + NQ * NT;
    int row = blockIdx.x * 8 + (threadIdx.x >> 5);
    int lane = threadIdx.x & 31;
    if (row >= NROWS) return;
    const float* src;
    __nv_bfloat16* dst;
    if (row < NROWS_V) {
        src = g_vtok_f32 + (size_t)row * NE;
        dst = g_vtok + (size_t)row * NE;
    } else {
        src = g_ttok_f32 + (size_t)(row - NROWS_V) * NE;
        dst = g_ttok + (size_t)(row - NROWS_V) * NE;
    }
    const float4* p4 = (const float4*)src;
    float s = 0.f;
#pragma unroll
    for (int i = lane; i < NE / 4; i += 32) {
        float4 v = p4[i];
        s += v.x * v.x + v.y * v.y + v.z * v.z + v.w * v.w;
    }
#pragma unroll
    for (int off = 16; off > 0; off >>= 1)
        s += __shfl_xor_sync(0xffffffffu, s, off);
    float inv = 1.f / fmaxf(sqrtf(s), 1e-12f);
    __nv_bfloat162* d2 = (__nv_bfloat162*)dst;
#pragma unroll
    for (int i = lane; i < NE / 4; i += 32) {
        float4 v = p4[i];
        d2[2 * i]     = __float22bfloat162_rn(make_float2(v.x * inv, v.y * inv));
        d2[2 * i + 1] = __float22bfloat162_rn(make_float2(v.z * inv, v.w * inv));
    }
}

// ===========================================================================
// Stage 2: one CTA = (b, q-pair). cp.async double-buffered staging.
//   M=256 (197 pad), N=160 (2 q x 80), K=512 in 8x64 chunks.
//   512 thr / 16 warps: 8 m-warps x 2 q-warps; warp tile 32 x 80.
// ===========================================================================
#define APITCH 144
#define BOFF2  (256 * APITCH)                  // 36864
#define STAGE  (BOFF2 + 160 * APITCH)          // 59904
#define LWP2   161                             // logits pitch (2q x 80 + 1)
#define SMEM_DYN 126880                        // >= max(2*STAGE=119808, logits 126868)

__global__ __launch_bounds__(512, 1) void stage2(
    const int* __restrict__ text_length,
    float* __restrict__ t2v, float* __restrict__ v2t)
{
    extern __shared__ __align__(16) char dsm[];
    __shared__ float s_t0[512], s_t1[512], s_v0[512], s_v1[512];

    const int tid = threadIdx.x;
    const int wid = tid >> 5, lane = tid & 31;
    const int qb = blockIdx.x, b = blockIdx.y;   // q pair = {2qb, 2qb+1}

    const uint4* Va  = (const uint4*)(g_vtok + (size_t)b * NV * NE);       // 64 u4/row
    const uint4* Tt0 = (const uint4*)(g_ttok + (size_t)(2 * qb) * NT * NE);
    const uint4* Tt1 = (const uint4*)(g_ttok + (size_t)(2 * qb + 1) * NT * NE);

    const uint32_t st0 = smem_u32(dsm);
    const uint32_t st1 = st0 + STAGE;

    const int mrow = (wid & 7) * 32;             // 8 m-warps
    const int ncol = (wid >> 3) * 80;            // 2 q-warp-groups

    // ldmatrix base offsets (relative; add stage base per iteration)
    const uint32_t aoff = (uint32_t)(mrow + (lane & 7) + ((lane >> 3) & 1) * 8) * APITCH
                        + (uint32_t)(lane >> 4) * 16;
    const uint32_t boff = BOFF2
                        + (uint32_t)(ncol + (lane & 7)) * APITCH
                        + (uint32_t)((lane >> 3) & 1) * 16;

    float c[2][10][4];
#pragma unroll
    for (int mi = 0; mi < 2; mi++)
#pragma unroll
        for (int ni = 0; ni < 10; ni++)
#pragma unroll
            for (int j = 0; j < 4; j++) c[mi][ni][j] = 0.f;

    // ---- cp.async chunk issue ----
    auto issue = [&](int ch, uint32_t sbase) {
        const int k4 = ch * 8;
#pragma unroll
        for (int it = 0; it < 4; it++) {
            int slot = it * 512 + tid, row = slot >> 3, seg = slot & 7;
            bool ok = row < NV;
            const uint4* src = Va + (ok ? row * 64 : 0) + k4 + seg;
            cp16(sbase + (uint32_t)(row * APITCH + seg * 16), src, ok);
        }
#pragma unroll
        for (int it = 0; it < 3; it++) {
            int slot = it * 512 + tid;
            if (slot < 1280) {
                int rbb = slot >> 3, seg = slot & 7;
                int trow = (rbb < 80) ? rbb : rbb - 80;
                bool ok = trow < NT;
                const uint4* base = (rbb < 80) ? Tt0 : Tt1;
                const uint4* src = base + (ok ? trow * 64 : 0) + k4 + seg;
                cp16(sbase + (uint32_t)(BOFF2 + rbb * APITCH + seg * 16), src, ok);
            }
        }
    };

    issue(0, st0); CP_COMMIT();
    issue(1, st1); CP_COMMIT();

    for (int ch = 0; ch < 8; ch++) {
        if (ch == 7) asm volatile("cp.async.wait_group 0;" ::: "memory");
        else         asm volatile("cp.async.wait_group 1;" ::: "memory");
        __syncthreads();

        const uint32_t sb = (ch & 1) ? st1 : st0;
        const uint32_t aa = sb + aoff, ba = sb + boff;
#pragma unroll
        for (int ks = 0; ks < 4; ks++) {
            uint32_t af[2][4], bf[10][2];
#pragma unroll
            for (int mi = 0; mi < 2; mi++)
                ldmatrix_x4(af[mi], aa + mi * (16 * APITCH) + ks * 32);
#pragma unroll
            for (int ni = 0; ni < 10; ni++)
                ldmatrix_x2(bf[ni], ba + ni * (8 * APITCH) + ks * 32);
#pragma unroll
            for (int mi = 0; mi < 2; mi++)
#pragma unroll
                for (int ni = 0; ni < 10; ni++)
                    mma_16816(c[mi][ni], af[mi], bf[ni]);
        }
        __syncthreads();
        if (ch + 2 < 8) { issue(ch + 2, sb); CP_COMMIT(); }
    }

    // ---- spill frags to SMEM logits [197 x (2x80)] ----
    float* logits = (float*)dsm;
#pragma unroll
    for (int mi = 0; mi < 2; mi++) {
#pragma unroll
        for (int ni = 0; ni < 10; ni++) {
            int r0 = mrow + mi * 16 + (lane >> 2);
            int tloc = ni * 8 + ((lane & 3) << 1);
            int cc = ncol + tloc;
            float* cf = c[mi][ni];
            if (tloc < NT) {
                if (r0 < NV)     logits[r0 * LWP2 + cc] = cf[0];
                if (r0 + 8 < NV) logits[(r0 + 8) * LWP2 + cc] = cf[2];
            }
            if (tloc + 1 < NT) {
                if (r0 < NV)     logits[r0 * LWP2 + cc + 1] = cf[1];
                if (r0 + 8 < NV) logits[(r0 + 8) * LWP2 + cc + 1] = cf[3];
            }
        }
    }
    __syncthreads();

    const int len0 = text_length[2 * qb];
    const int len1 = text_length[2 * qb + 1];

    float pt0 = 0.f, pt1 = 0.f, pv0 = 0.f, pv1 = 0.f;

    // t2v: 154 threads, one per (qq, t)
    if (tid < 2 * NT) {
        int qq = (tid >= NT) ? 1 : 0;
        int t = tid - qq * NT;
        int col = qq * 80 + t;
        float cm = -INFINITY;
        for (int v = 0; v < NV; v++) cm = fmaxf(cm, logits[v * LWP2 + col]);
        int len = qq ? len1 : len0;
        if (t < len) { if (qq) pt1 = cm; else pt0 = cm; }
    }
    // v2t: 394 items = (qq, v)
    for (int idx = tid; idx < 2 * NV; idx += 512) {
        int qq = (idx >= NV) ? 1 : 0;
        int v = idx - qq * NV;
        int len = qq ? len1 : len0;
        const float* lrow = logits + v * LWP2 + qq * 80;
        float m = -INFINITY;
        for (int t = 0; t < NT; t++) {
            float val = (t < len) ? lrow[t] : 0.f;
            m = fmaxf(m, val);
        }
        if (qq) pv1 += m; else pv0 += m;
    }
    s_t0[tid] = pt0; s_t1[tid] = pt1; s_v0[tid] = pv0; s_v1[tid] = pv1;
    __syncthreads();
#pragma unroll
    for (int s = 256; s > 0; s >>= 1) {
        if (tid < s) {
            s_t0[tid] += s_t0[tid + s];
            s_t1[tid] += s_t1[tid + s];
            s_v0[tid] += s_v0[tid + s];
            s_v1[tid] += s_v1[tid + s];
        }
        __syncthreads();
    }
    if (tid == 0) {
        t2v[b * NQ + 2 * qb]     = s_t0[0] / (float)len0;
        t2v[b * NQ + 2 * qb + 1] = s_t1[0] / (float)len1;
        v2t[b * NQ + 2 * qb]     = s_v0[0] / (float)NV;
        v2t[b * NQ + 2 * qb + 1] = s_v1[0] / (float)NV;
    }
}

// ===========================================================================
extern "C" void kernel_launch(void* const* d_in, const int* in_sizes, int n_in,
                              void* d_out, int out_size)
{
    const float* visual_cls     = (const float*)d_in[0];
    const float* visual_tokens  = (const float*)d_in[1];
    const float* textual_cls    = (const float*)d_in[2];
    const float* textual_tokens = (const float*)d_in[3];
    const float* Wv_cls = (const float*)d_in[4];
    const float* bv_cls = (const float*)d_in[5];
    const float* Wt_cls = (const float*)d_in[6];
    const float* bt_cls = (const float*)d_in[7];
    const float* Wv_tok = (const float*)d_in[8];
    const float* bv_tok = (const float*)d_in[9];
    const float* Wt_tok = (const float*)d_in[10];
    const float* bt_tok = (const float*)d_in[11];
    const int*   text_length = (const int*)d_in[12];

    float* out = (float*)d_out;
    float* o_vcls = out;
    float* o_tcls = out + NB * NE;
    float* o_t2v  = out + 2 * NB * NE;
    float* o_v2t  = o_t2v + NB * NQ;

    float *pv, *pt;
    cudaGetSymbolAddress((void**)&pv, g_vtok_f32);
    cudaGetSymbolAddress((void**)&pt, g_ttok_f32);

    proj_gemm<<<dim3(2, 8), 256>>>(visual_cls, Wv_cls, bv_cls, o_vcls, NB);
    proj_gemm<<<dim3(2, 8), 256>>>(textual_cls, Wt_cls, bt_cls, o_tcls, NQ);

    proj_mma<<<dim3((NB * NV + 127) / 128, 4), 256>>>(visual_tokens, Wv_tok, bv_tok, pv, NB * NV);
    proj_mma<<<dim3((NQ * NT + 127) / 128, 4), 256>>>(textual_tokens, Wt_tok, bt_tok, pt, NQ * NT);

    l2norm_rows<<<(NB * NV + NQ * NT + 7) / 8, 256>>>();

    cudaFuncSetAttribute(stage2, cudaFuncAttributeMaxDynamicSharedMemorySize, SMEM_DYN);
    stage2<<<dim3(NQ / 2, NB), 512, SMEM_DYN>>>(text_length, o_t2v, o_v2t);
}

// round 7
// speedup vs baseline: 6.9997x; 1.1896x over previous
#include <cuda_runtime.h>
#include <cuda_bf16.h>
#include <math.h>
#include <stdint.h>

// Problem dims (fixed)
#define NB 96
#define NQ 96
#define NV 197
#define NT 77
#define ND 768
#define NE 512

__device__ float         g_vtok_f32[(size_t)NB * NV * NE];
__device__ float         g_ttok_f32[(size_t)NQ * NT * NE];
__device__ __nv_bfloat16 g_vtok[(size_t)NB * NV * NE];
__device__ __nv_bfloat16 g_ttok[(size_t)NQ * NT * NE];

__device__ __forceinline__ uint32_t smem_u32(const void* p) {
    uint32_t a;
    asm("{ .reg .u64 t; cvta.to.shared.u64 t, %1; cvt.u32.u64 %0, t; }"
        : "=r"(a) : "l"(p));
    return a;
}
__device__ __forceinline__ void ldmatrix_x4(uint32_t* r, uint32_t addr) {
    asm volatile("ldmatrix.sync.aligned.m8n8.x4.shared.b16 {%0,%1,%2,%3}, [%4];"
        : "=r"(r[0]), "=r"(r[1]), "=r"(r[2]), "=r"(r[3]) : "r"(addr));
}
__device__ __forceinline__ void ldmatrix_x2(uint32_t* r, uint32_t addr) {
    asm volatile("ldmatrix.sync.aligned.m8n8.x2.shared.b16 {%0,%1}, [%2];"
        : "=r"(r[0]), "=r"(r[1]) : "r"(addr));
}
__device__ __forceinline__ void mma_16816(float* c, const uint32_t* a, const uint32_t* b) {
    asm volatile("mma.sync.aligned.m16n8k16.row.col.f32.bf16.bf16.f32 "
        "{%0,%1,%2,%3}, {%4,%5,%6,%7}, {%8,%9}, {%0,%1,%2,%3};"
        : "+f"(c[0]), "+f"(c[1]), "+f"(c[2]), "+f"(c[3])
        : "r"(a[0]), "r"(a[1]), "r"(a[2]), "r"(a[3]), "r"(b[0]), "r"(b[1]));
}
__device__ __forceinline__ void cp16(uint32_t dst, const void* src, bool pred) {
    int sz = pred ? 16 : 0;
    asm volatile("cp.async.cg.shared.global [%0], [%1], 16, %2;"
        :: "r"(dst), "l"(src), "r"(sz) : "memory");
}
#define CP_COMMIT() asm volatile("cp.async.commit_group;" ::: "memory")
__device__ __forceinline__ uint4 f32x8_bf16(float4 a, float4 b) {
    uint4 r;
    __nv_bfloat162 p;
    p = __float22bfloat162_rn(make_float2(a.x, a.y)); r.x = *(uint32_t*)&p;
    p = __float22bfloat162_rn(make_float2(a.z, a.w)); r.y = *(uint32_t*)&p;
    p = __float22bfloat162_rn(make_float2(b.x, b.y)); r.z = *(uint32_t*)&p;
    p = __float22bfloat162_rn(make_float2(b.z, b.w)); r.w = *(uint32_t*)&p;
    return r;
}

// ===========================================================================
// cls projection GEMM (exact fp32 SIMT)
// ===========================================================================
__global__ __launch_bounds__(256) void proj_gemm(
    const float* __restrict__ X, const float* __restrict__ W,
    const float* __restrict__ bias, float* __restrict__ Y, int R)
{
    __shared__ float As[16][68];
    __shared__ float Bs[16][68];
    const int r0 = blockIdx.x * 64, e0 = blockIdx.y * 64;
    const int tid = threadIdx.x;
    const int ty = tid >> 4, tx = tid & 15;
    const int lrow = tid >> 2, lk4 = tid & 3;

    float acc[4][4];
#pragma unroll
    for (int i = 0; i < 4; i++)
#pragma unroll
        for (int j = 0; j < 4; j++) acc[i][j] = 0.f;

    const int r_ld = r0 + lrow;
    const float4 zero4 = make_float4(0.f, 0.f, 0.f, 0.f);

    for (int k0 = 0; k0 < ND; k0 += 16) {
        float4 av = (r_ld < R)
            ? *(const float4*)(X + (size_t)r_ld * ND + k0 + lk4 * 4) : zero4;
        float4 bv = *(const float4*)(W + (size_t)(e0 + lrow) * ND + k0 + lk4 * 4);
        __syncthreads();
        As[lk4 * 4 + 0][lrow] = av.x; As[lk4 * 4 + 1][lrow] = av.y;
        As[lk4 * 4 + 2][lrow] = av.z; As[lk4 * 4 + 3][lrow] = av.w;
        Bs[lk4 * 4 + 0][lrow] = bv.x; Bs[lk4 * 4 + 1][lrow] = bv.y;
        Bs[lk4 * 4 + 2][lrow] = bv.z; Bs[lk4 * 4 + 3][lrow] = bv.w;
        __syncthreads();
#pragma unroll
        for (int kk = 0; kk < 16; kk++) {
            float4 a = *(const float4*)&As[kk][ty * 4];
            float4 b = *(const float4*)&Bs[kk][tx * 4];
            float aa[4] = {a.x, a.y, a.z, a.w};
            float bb[4] = {b.x, b.y, b.z, b.w};
#pragma unroll
            for (int i = 0; i < 4; i++)
#pragma unroll
                for (int j = 0; j < 4; j++)
                    acc[i][j] = fmaf(aa[i], bb[j], acc[i][j]);
        }
    }
#pragma unroll
    for (int i = 0; i < 4; i++) {
        int r = r0 + ty * 4 + i;
        if (r < R) {
#pragma unroll
            for (int j = 0; j < 4; j++) {
                int e = e0 + tx * 4 + j;
                Y[(size_t)r * NE + e] = acc[i][j] + bias[e];
            }
        }
    }
}

// ===========================================================================
// Token projection via mma.sync bf16
// ===========================================================================
#define PPITCH 144

__global__ __launch_bounds__(256) void proj_mma(
    const float* __restrict__ X, const float* __restrict__ W,
    const float* __restrict__ bias, float* __restrict__ Y, int R)
{
    __shared__ __align__(16) char sm[2 * 128 * PPITCH];
    char* smA = sm;
    char* smB = sm + 128 * PPITCH;
    const int tid = threadIdx.x, wid = tid >> 5, lane = tid & 31;
    const int r0 = blockIdx.x * 128, e0 = blockIdx.y * 128;
    const int mrow = (wid & 3) * 32, ncol = (wid >> 2) * 64;

    const uint32_t aaddr = smem_u32(smA)
        + (uint32_t)(mrow + (lane & 7) + ((lane >> 3) & 1) * 8) * PPITCH
        + (uint32_t)(lane >> 4) * 16;
    const uint32_t baddr = smem_u32(smB)
        + (uint32_t)(ncol + (lane & 7)) * PPITCH
        + (uint32_t)((lane >> 3) & 1) * 16;

    float c[2][8][4];
#pragma unroll
    for (int mi = 0; mi < 2; mi++)
#pragma unroll
        for (int ni = 0; ni < 8; ni++)
#pragma unroll
            for (int j = 0; j < 4; j++) c[mi][ni][j] = 0.f;

    const int row = tid >> 3, seg = tid & 7;
    uint4 pa[4], pb[4];

#pragma unroll
    for (int it = 0; it < 4; it++) {
        int rr = r0 + it * 32 + row;
        if (rr < R) {
            const float4* p = (const float4*)(X + (size_t)rr * ND + seg * 8);
            pa[it] = f32x8_bf16(p[0], p[1]);
        } else pa[it] = make_uint4(0, 0, 0, 0);
        const float4* pw = (const float4*)(W + (size_t)(e0 + it * 32 + row) * ND + seg * 8);
        pb[it] = f32x8_bf16(pw[0], pw[1]);
    }

    for (int ch = 0; ch < 12; ch++) {
        __syncthreads();
#pragma unroll
        for (int it = 0; it < 4; it++) {
            *(uint4*)(smA + (it * 32 + row) * PPITCH + seg * 16) = pa[it];
            *(uint4*)(smB + (it * 32 + row) * PPITCH + seg * 16) = pb[it];
        }
        __syncthreads();

        if (ch < 11) {
            int k0 = (ch + 1) * 64;
#pragma unroll
            for (int it = 0; it < 4; it++) {
                int rr = r0 + it * 32 + row;
                if (rr < R) {
                    const float4* p = (const float4*)(X + (size_t)rr * ND + k0 + seg * 8);
                    pa[it] = f32x8_bf16(p[0], p[1]);
                } else pa[it] = make_uint4(0, 0, 0, 0);
                const float4* pw = (const float4*)(W + (size_t)(e0 + it * 32 + row) * ND + k0 + seg * 8);
                pb[it] = f32x8_bf16(pw[0], pw[1]);
            }
        }

#pragma unroll
        for (int ks = 0; ks < 4; ks++) {
            uint32_t af[2][4], bf[8][2];
#pragma unroll
            for (int mi = 0; mi < 2; mi++)
                ldmatrix_x4(af[mi], aaddr + mi * (16 * PPITCH) + ks * 32);
#pragma unroll
            for (int ni = 0; ni < 8; ni++)
                ldmatrix_x2(bf[ni], baddr + ni * (8 * PPITCH) + ks * 32);
#pragma unroll
            for (int mi = 0; mi < 2; mi++)
#pragma unroll
                for (int ni = 0; ni < 8; ni++)
                    mma_16816(c[mi][ni], af[mi], bf[ni]);
        }
    }

#pragma unroll
    for (int mi = 0; mi < 2; mi++) {
        int rr = r0 + mrow + mi * 16 + (lane >> 2);
        if (rr < R) {
#pragma unroll
            for (int ni = 0; ni < 8; ni++) {
                int e = e0 + ncol + ni * 8 + ((lane & 3) << 1);
                float2 o;
                o.x = c[mi][ni][0] + bias[e];
                o.y = c[mi][ni][1] + bias[e + 1];
                *(float2*)(Y + (size_t)rr * NE + e) = o;
                o.x = c[mi][ni][2] + bias[e];
                o.y = c[mi][ni][3] + bias[e + 1];
                *(float2*)(Y + (size_t)(rr + 8) * NE + e) = o;
            }
        }
    }
}

// ===========================================================================
// L2-normalize rows (fp32 in), write bf16 operand buffers
// ===========================================================================
__global__ __launch_bounds__(256) void l2norm_rows()
{
    const int NROWS_V = NB * NV;
    const int NROWS = NROWS_V + NQ * NT;
    int row = blockIdx.x * 8 + (threadIdx.x >> 5);
    int lane = threadIdx.x & 31;
    if (row >= NROWS) return;
    const float* src;
    __nv_bfloat16* dst;
    if (row < NROWS_V) {
        src = g_vtok_f32 + (size_t)row * NE;
        dst = g_vtok + (size_t)row * NE;
    } else {
        src = g_ttok_f32 + (size_t)(row - NROWS_V) * NE;
        dst = g_ttok + (size_t)(row - NROWS_V) * NE;
    }
    const float4* p4 = (const float4*)src;
    float s = 0.f;
#pragma unroll
    for (int i = lane; i < NE / 4; i += 32) {
        float4 v = p4[i];
        s += v.x * v.x + v.y * v.y + v.z * v.z + v.w * v.w;
    }
#pragma unroll
    for (int off = 16; off > 0; off >>= 1)
        s += __shfl_xor_sync(0xffffffffu, s, off);
    float inv = 1.f / fmaxf(sqrtf(s), 1e-12f);
    __nv_bfloat162* d2 = (__nv_bfloat162*)dst;
#pragma unroll
    for (int i = lane; i < NE / 4; i += 32) {
        float4 v = p4[i];
        d2[2 * i]     = __float22bfloat162_rn(make_float2(v.x * inv, v.y * inv));
        d2[2 * i + 1] = __float22bfloat162_rn(make_float2(v.z * inv, v.w * inv));
    }
}

// ===========================================================================
// Stage 2: one CTA = (b, q-pair). 3-stage cp.async, register/shfl epilogue.
//   M=256 (197 pad), N=160 (2 q x 80), K=512 in 8x64 chunks.
//   512 thr / 16 warps: 8 m-warps x 2 q-groups; warp tile 32 x 80.
// ===========================================================================
#define APITCH 144
#define BOFF2  (256 * APITCH)                  // 36864
#define STAGE  (BOFF2 + 160 * APITCH)          // 59904
#define SMEM_DYN (3 * STAGE)                   // 179712
#define NINF   (-INFINITY)

__global__ __launch_bounds__(512, 1) void stage2(
    const int* __restrict__ text_length,
    float* __restrict__ t2v, float* __restrict__ v2t)
{
    extern __shared__ __align__(16) char dsm[];
    __shared__ float s_colmax[8][164];
    __shared__ float s_vsum[16];
    __shared__ float s_tred[256];

    const int tid = threadIdx.x;
    const int wid = tid >> 5, lane = tid & 31;
    const int qb = blockIdx.x, b = blockIdx.y;   // q pair = {2qb, 2qb+1}

    const int len0 = text_length[2 * qb];
    const int len1 = text_length[2 * qb + 1];

    const uint4* Va  = (const uint4*)(g_vtok + (size_t)b * NV * NE);
    const uint4* Tt0 = (const uint4*)(g_ttok + (size_t)(2 * qb) * NT * NE);
    const uint4* Tt1 = (const uint4*)(g_ttok + (size_t)(2 * qb + 1) * NT * NE);

    const uint32_t st[3] = { smem_u32(dsm), smem_u32(dsm) + STAGE,
                             smem_u32(dsm) + 2 * STAGE };

    const int mrow = (wid & 7) * 32;             // 8 m-warps
    const int myq  = wid >> 3;                   // q-group of this warp
    const int ncol = myq * 80;

    const uint32_t aoff = (uint32_t)(mrow + (lane & 7) + ((lane >> 3) & 1) * 8) * APITCH
                        + (uint32_t)(lane >> 4) * 16;
    // B x4 ldmatrix: mats 0,1 = n-tile 2nn (k0-7,k8-15); mats 2,3 = n-tile 2nn+1
    const uint32_t boff = BOFF2
                        + (uint32_t)(ncol + (lane & 7) + ((lane >> 4) << 3)) * APITCH
                        + (uint32_t)((lane >> 3) & 1) * 16;

    float c[2][10][4];
#pragma unroll
    for (int mi = 0; mi < 2; mi++)
#pragma unroll
        for (int ni = 0; ni < 10; ni++)
#pragma unroll
            for (int j = 0; j < 4; j++) c[mi][ni][j] = 0.f;

    auto issue = [&](int ch, uint32_t sbase) {
        const int k4 = ch * 8;
#pragma unroll
        for (int it = 0; it < 4; it++) {
            int slot = it * 512 + tid, row = slot >> 3, seg = slot & 7;
            bool ok = row < NV;
            const uint4* src = Va + (ok ? row * 64 : 0) + k4 + seg;
            cp16(sbase + (uint32_t)(row * APITCH + seg * 16), src, ok);
        }
#pragma unroll
        for (int it = 0; it < 3; it++) {
            int slot = it * 512 + tid;
            if (slot < 1280) {
                int rbb = slot >> 3, seg = slot & 7;
                int trow = (rbb < 80) ? rbb : rbb - 80;
                bool ok = trow < NT;
                const uint4* base = (rbb < 80) ? Tt0 : Tt1;
                const uint4* src = base + (ok ? trow * 64 : 0) + k4 + seg;
                cp16(sbase + (uint32_t)(BOFF2 + rbb * APITCH + seg * 16), src, ok);
            }
        }
    };

    issue(0, st[0]); CP_COMMIT();
    issue(1, st[1]); CP_COMMIT();
    issue(2, st[2]); CP_COMMIT();

    for (int ch = 0; ch < 8; ch++) {
        if (ch < 6)      asm volatile("cp.async.wait_group 2;" ::: "memory");
        else if (ch == 6) asm volatile("cp.async.wait_group 1;" ::: "memory");
        else              asm volatile("cp.async.wait_group 0;" ::: "memory");
        __syncthreads();

        const uint32_t sb = st[ch % 3];
        const uint32_t aa = sb + aoff, ba = sb + boff;
#pragma unroll
        for (int ks = 0; ks < 4; ks++) {
            uint32_t af[2][4], bf[20];
#pragma unroll
            for (int mi = 0; mi < 2; mi++)
                ldmatrix_x4(af[mi], aa + mi * (16 * APITCH) + ks * 32);
#pragma unroll
            for (int nn = 0; nn < 5; nn++)
                ldmatrix_x4(bf + nn * 4, ba + nn * (16 * APITCH) + ks * 32);
#pragma unroll
            for (int mi = 0; mi < 2; mi++)
#pragma unroll
                for (int ni = 0; ni < 10; ni++)
                    mma_16816(c[mi][ni], af[mi], bf + ni * 2);
        }
        __syncthreads();
        if (ch + 3 < 8) { issue(ch + 3, sb); CP_COMMIT(); }
    }

    // ================= register/shfl epilogue =================
    const int mylen = myq ? len1 : len0;
    const int rb = mrow + (lane >> 2);

    float rowmax[2][2] = {{NINF, NINF}, {NINF, NINF}};
    float colmax[10][2];
#pragma unroll
    for (int ni = 0; ni < 10; ni++) { colmax[ni][0] = NINF; colmax[ni][1] = NINF; }

#pragma unroll
    for (int mi = 0; mi < 2; mi++) {
        int r0 = rb + mi * 16;
        bool v0 = r0 < NV, v8 = (r0 + 8) < NV;
#pragma unroll
        for (int ni = 0; ni < 10; ni++) {
            int tl = ni * 8 + ((lane & 3) << 1);
            float* cf = c[mi][ni];
            // v2t row-max: masked logit (t<len: value; len<=t<NT: 0; pad: -inf)
            float m0 = (tl     < mylen) ? cf[0] : ((tl     < NT) ? 0.f : NINF);
            float m1 = (tl + 1 < mylen) ? cf[1] : ((tl + 1 < NT) ? 0.f : NINF);
            float m2 = (tl     < mylen) ? cf[2] : ((tl     < NT) ? 0.f : NINF);
            float m3 = (tl + 1 < mylen) ? cf[3] : ((tl + 1 < NT) ? 0.f : NINF);
            rowmax[mi][0] = fmaxf(rowmax[mi][0], fmaxf(m0, m1));
            rowmax[mi][1] = fmaxf(rowmax[mi][1], fmaxf(m2, m3));
            // t2v col-max over valid v rows
            colmax[ni][0] = fmaxf(colmax[ni][0],
                fmaxf(v0 ? cf[0] : NINF, v8 ? cf[2] : NINF));
            colmax[ni][1] = fmaxf(colmax[ni][1],
                fmaxf(v0 ? cf[1] : NINF, v8 ? cf[3] : NINF));
        }
    }

    // reduce row maxes across the quad (lanes sharing a row)
#pragma unroll
    for (int mi = 0; mi < 2; mi++)
#pragma unroll
        for (int h = 0; h < 2; h++) {
            float r = rowmax[mi][h];
            r = fmaxf(r, __shfl_xor_sync(0xffffffffu, r, 1));
            r = fmaxf(r, __shfl_xor_sync(0xffffffffu, r, 2));
            rowmax[mi][h] = r;
        }
    float rowsum = 0.f;
#pragma unroll
    for (int mi = 0; mi < 2; mi++) {
        int r0 = rb + mi * 16;
        if (r0 < NV)     rowsum += rowmax[mi][0];
        if (r0 + 8 < NV) rowsum += rowmax[mi][1];
    }
    rowsum += __shfl_xor_sync(0xffffffffu, rowsum, 4);
    rowsum += __shfl_xor_sync(0xffffffffu, rowsum, 8);
    rowsum += __shfl_xor_sync(0xffffffffu, rowsum, 16);
    if (lane == 0) s_vsum[wid] = rowsum;

    // reduce col maxes across row-groups (lanes sharing a column)
#pragma unroll
    for (int ni = 0; ni < 10; ni++)
#pragma unroll
        for (int h = 0; h < 2; h++) {
            float r = colmax[ni][h];
            r = fmaxf(r, __shfl_xor_sync(0xffffffffu, r, 4));
            r = fmaxf(r, __shfl_xor_sync(0xffffffffu, r, 8));
            r = fmaxf(r, __shfl_xor_sync(0xffffffffu, r, 16));
            colmax[ni][h] = r;
        }
    if (lane < 4) {
#pragma unroll
        for (int ni = 0; ni < 10; ni++) {
            int cc = ncol + ni * 8 + (lane << 1);
            s_colmax[wid & 7][cc]     = colmax[ni][0];
            s_colmax[wid & 7][cc + 1] = colmax[ni][1];
        }
    }
    __syncthreads();

    if (tid < 256) {
        int qq = tid >> 7, cl = tid & 127;
        float val = 0.f;
        if (cl < 80) {
            float cm = NINF;
#pragma unroll
            for (int w = 0; w < 8; w++) cm = fmaxf(cm, s_colmax[w][qq * 80 + cl]);
            int len = qq ? len1 : len0;
            val = (cl < len) ? cm : 0.f;
        }
        s_tred[tid] = val;
    }
    __syncthreads();
#pragma unroll
    for (int s = 64; s > 0; s >>= 1) {
        if (tid < 256 && (tid & 127) < s) s_tred[tid] += s_tred[tid + s];
        __syncthreads();
    }
    if (tid == 0) {
        float v0s = 0.f, v1s = 0.f;
#pragma unroll
        for (int w = 0; w < 8; w++) { v0s += s_vsum[w]; v1s += s_vsum[8 + w]; }
        t2v[b * NQ + 2 * qb]     = s_tred[0]   / (float)len0;
        t2v[b * NQ + 2 * qb + 1] = s_tred[128] / (float)len1;
        v2t[b * NQ + 2 * qb]     = v0s / (float)NV;
        v2t[b * NQ + 2 * qb + 1] = v1s / (float)NV;
    }
}

// ===========================================================================
extern "C" void kernel_launch(void* const* d_in, const int* in_sizes, int n_in,
                              void* d_out, int out_size)
{
    const float* visual_cls     = (const float*)d_in[0];
    const float* visual_tokens  = (const float*)d_in[1];
    const float* textual_cls    = (const float*)d_in[2];
    const float* textual_tokens = (const float*)d_in[3];
    const float* Wv_cls = (const float*)d_in[4];
    const float* bv_cls = (const float*)d_in[5];
    const float* Wt_cls = (const float*)d_in[6];
    const float* bt_cls = (const float*)d_in[7];
    const float* Wv_tok = (const float*)d_in[8];
    const float* bv_tok = (const float*)d_in[9];
    const float* Wt_tok = (const float*)d_in[10];
    const float* bt_tok = (const float*)d_in[11];
    const int*   text_length = (const int*)d_in[12];

    float* out = (float*)d_out;
    float* o_vcls = out;
    float* o_tcls = out + NB * NE;
    float* o_t2v  = out + 2 * NB * NE;
    float* o_v2t  = o_t2v + NB * NQ;

    float *pv, *pt;
    cudaGetSymbolAddress((void**)&pv, g_vtok_f32);
    cudaGetSymbolAddress((void**)&pt, g_ttok_f32);

    proj_gemm<<<dim3(2, 8), 256>>>(visual_cls, Wv_cls, bv_cls, o_vcls, NB);
    proj_gemm<<<dim3(2, 8), 256>>>(textual_cls, Wt_cls, bt_cls, o_tcls, NQ);

    proj_mma<<<dim3((NB * NV + 127) / 128, 4), 256>>>(visual_tokens, Wv_tok, bv_tok, pv, NB * NV);
    proj_mma<<<dim3((NQ * NT + 127) / 128, 4), 256>>>(textual_tokens, Wt_tok, bt_tok, pt, NQ * NT);

    l2norm_rows<<<(NB * NV + NQ * NT + 7) / 8, 256>>>();

    cudaFuncSetAttribute(stage2, cudaFuncAttributeMaxDynamicSharedMemorySize, SMEM_DYN);
    stage2<<<dim3(NQ / 2, NB), 512, SMEM_DYN>>>(text_length, o_t2v, o_v2t);
}

// round 8
// speedup vs baseline: 7.6547x; 1.0936x over previous
#include <cuda_runtime.h>
#include <cuda_bf16.h>
#include <math.h>
#include <stdint.h>

// Problem dims (fixed)
#define NB 96
#define NQ 96
#define NV 197
#define NT 77
#define ND 768
#define NE 512

__device__ float         g_vtok_f32[(size_t)NB * NV * NE];
__device__ float         g_ttok_f32[(size_t)NQ * NT * NE];
__device__ __nv_bfloat16 g_vtok[(size_t)NB * NV * NE];
__device__ __nv_bfloat16 g_ttok[(size_t)NQ * NT * NE];
// bf16 pre-converted GEMM inputs
__device__ __nv_bfloat16 g_xvb[(size_t)NB * NV * ND];
__device__ __nv_bfloat16 g_xtb[(size_t)NQ * NT * ND];
__device__ __nv_bfloat16 g_wvb[(size_t)NE * ND];
__device__ __nv_bfloat16 g_wtb[(size_t)NE * ND];

__device__ __forceinline__ uint32_t smem_u32(const void* p) {
    uint32_t a;
    asm("{ .reg .u64 t; cvta.to.shared.u64 t, %1; cvt.u32.u64 %0, t; }"
        : "=r"(a) : "l"(p));
    return a;
}
__device__ __forceinline__ void ldmatrix_x4(uint32_t* r, uint32_t addr) {
    asm volatile("ldmatrix.sync.aligned.m8n8.x4.shared.b16 {%0,%1,%2,%3}, [%4];"
        : "=r"(r[0]), "=r"(r[1]), "=r"(r[2]), "=r"(r[3]) : "r"(addr));
}
__device__ __forceinline__ void mma_16816(float* c, const uint32_t* a, const uint32_t* b) {
    asm volatile("mma.sync.aligned.m16n8k16.row.col.f32.bf16.bf16.f32 "
        "{%0,%1,%2,%3}, {%4,%5,%6,%7}, {%8,%9}, {%0,%1,%2,%3};"
        : "+f"(c[0]), "+f"(c[1]), "+f"(c[2]), "+f"(c[3])
        : "r"(a[0]), "r"(a[1]), "r"(a[2]), "r"(a[3]), "r"(b[0]), "r"(b[1]));
}
__device__ __forceinline__ void cp16(uint32_t dst, const void* src, bool pred) {
    int sz = pred ? 16 : 0;
    asm volatile("cp.async.cg.shared.global [%0], [%1], 16, %2;"
        :: "r"(dst), "l"(src), "r"(sz) : "memory");
}
#define CP_COMMIT() asm volatile("cp.async.commit_group;" ::: "memory")
__device__ __forceinline__ uint4 f32x8_bf16(float4 a, float4 b) {
    uint4 r;
    __nv_bfloat162 p;
    p = __float22bfloat162_rn(make_float2(a.x, a.y)); r.x = *(uint32_t*)&p;
    p = __float22bfloat162_rn(make_float2(a.z, a.w)); r.y = *(uint32_t*)&p;
    p = __float22bfloat162_rn(make_float2(b.x, b.y)); r.z = *(uint32_t*)&p;
    p = __float22bfloat162_rn(make_float2(b.z, b.w)); r.w = *(uint32_t*)&p;
    return r;
}

// ===========================================================================
// Convert fp32 inputs -> bf16 operand buffers (one flat pass, 8 elems/thread)
// ===========================================================================
#define CSEG0 ((size_t)NB * NV * ND)                  // visual tokens
#define CSEG1 (CSEG0 + (size_t)NQ * NT * ND)          // + textual tokens
#define CSEG2 (CSEG1 + (size_t)NE * ND)               // + Wv_tok
#define CSEG3 (CSEG2 + (size_t)NE * ND)               // + Wt_tok

__global__ __launch_bounds__(256) void convert_bf16(
    const float* __restrict__ xv, const float* __restrict__ xt,
    const float* __restrict__ wv, const float* __restrict__ wt)
{
    size_t e = ((size_t)blockIdx.x * 256 + threadIdx.x) * 8;
    if (e >= CSEG3) return;
    const float* src;
    __nv_bfloat16* dst;
    size_t off;
    if (e < CSEG0)      { src = xv; dst = g_xvb; off = e; }
    else if (e < CSEG1) { src = xt; dst = g_xtb; off = e - CSEG0; }
    else if (e < CSEG2) { src = wv; dst = g_wvb; off = e - CSEG1; }
    else                { src = wt; dst = g_wtb; off = e - CSEG2; }
    const float4* p = (const float4*)(src + off);
    *(uint4*)(dst + off) = f32x8_bf16(p[0], p[1]);
}

// ===========================================================================
// cls projections (exact fp32 SIMT), both in one launch via blockIdx.z
// ===========================================================================
__global__ __launch_bounds__(256) void proj_cls(
    const float* __restrict__ Xv, const float* __restrict__ Wv,
    const float* __restrict__ bv, float* __restrict__ Yv,
    const float* __restrict__ Xt, const float* __restrict__ Wt,
    const float* __restrict__ bt, float* __restrict__ Yt)
{
    const float* X = blockIdx.z ? Xt : Xv;
    const float* W = blockIdx.z ? Wt : Wv;
    const float* bias = blockIdx.z ? bt : bv;
    float* Y = blockIdx.z ? Yt : Yv;
    const int R = NB;   // NB == NQ == 96

    __shared__ float As[16][68];
    __shared__ float Bs[16][68];
    const int r0 = blockIdx.x * 64, e0 = blockIdx.y * 64;
    const int tid = threadIdx.x;
    const int ty = tid >> 4, tx = tid & 15;
    const int lrow = tid >> 2, lk4 = tid & 3;

    float acc[4][4];
#pragma unroll
    for (int i = 0; i < 4; i++)
#pragma unroll
        for (int j = 0; j < 4; j++) acc[i][j] = 0.f;

    const int r_ld = r0 + lrow;
    const float4 zero4 = make_float4(0.f, 0.f, 0.f, 0.f);

    for (int k0 = 0; k0 < ND; k0 += 16) {
        float4 av = (r_ld < R)
            ? *(const float4*)(X + (size_t)r_ld * ND + k0 + lk4 * 4) : zero4;
        float4 bv4 = *(const float4*)(W + (size_t)(e0 + lrow) * ND + k0 + lk4 * 4);
        __syncthreads();
        As[lk4 * 4 + 0][lrow] = av.x; As[lk4 * 4 + 1][lrow] = av.y;
        As[lk4 * 4 + 2][lrow] = av.z; As[lk4 * 4 + 3][lrow] = av.w;
        Bs[lk4 * 4 + 0][lrow] = bv4.x; Bs[lk4 * 4 + 1][lrow] = bv4.y;
        Bs[lk4 * 4 + 2][lrow] = bv4.z; Bs[lk4 * 4 + 3][lrow] = bv4.w;
        __syncthreads();
#pragma unroll
        for (int kk = 0; kk < 16; kk++) {
            float4 a = *(const float4*)&As[kk][ty * 4];
            float4 b = *(const float4*)&Bs[kk][tx * 4];
            float aa[4] = {a.x, a.y, a.z, a.w};
            float bb[4] = {b.x, b.y, b.z, b.w};
#pragma unroll
            for (int i = 0; i < 4; i++)
#pragma unroll
                for (int j = 0; j < 4; j++)
                    acc[i][j] = fmaf(aa[i], bb[j], acc[i][j]);
        }
    }
#pragma unroll
    for (int i = 0; i < 4; i++) {
        int r = r0 + ty * 4 + i;
        if (r < R) {
#pragma unroll
            for (int j = 0; j < 4; j++) {
                int e = e0 + tx * 4 + j;
                Y[(size_t)r * NE + e] = acc[i][j] + bias[e];
            }
        }
    }
}

// ===========================================================================
// Token projection v2: pure-bf16 operands, 2-stage cp.async, 2 CTAs/SM.
//   BM=128, BN=128, BK=64 (12 chunks); z selects visual/textual job.
// ===========================================================================
#define PPITCH 144
#define PBOFF  (128 * PPITCH)                 // 18432
#define PSTAGE (2 * PBOFF)                    // 36864 per stage
#define VIS_BX 148                            // ceil(18912/128)
#define TEX_BX 58                             // ceil(7392/128)

__global__ __launch_bounds__(256, 2) void proj_mma2(
    const float* __restrict__ bias_v, const float* __restrict__ bias_t)
{
    const int z = blockIdx.z;
    if (z == 1 && blockIdx.x >= TEX_BX) return;
    const int R = z ? (NQ * NT) : (NB * NV);
    const uint4* Xb = (const uint4*)(z ? g_xtb : g_xvb);   // 96 u4 per row
    const uint4* Wb = (const uint4*)(z ? g_wtb : g_wvb);
    const float* bias = z ? bias_t : bias_v;
    float* Y = z ? g_ttok_f32 : g_vtok_f32;

    extern __shared__ __align__(16) char psm[];
    const uint32_t st0 = smem_u32(psm), st1 = st0 + PSTAGE;

    const int tid = threadIdx.x, wid = tid >> 5, lane = tid & 31;
    const int r0 = blockIdx.x * 128, e0 = blockIdx.y * 128;
    const int mrow = (wid & 3) * 32, ncol = (wid >> 2) * 64;

    const uint32_t aoff = (uint32_t)(mrow + (lane & 7) + ((lane >> 3) & 1) * 8) * PPITCH
                        + (uint32_t)(lane >> 4) * 16;
    const uint32_t boff = PBOFF
                        + (uint32_t)(ncol + (lane & 7) + ((lane >> 4) << 3)) * PPITCH
                        + (uint32_t)((lane >> 3) & 1) * 16;

    float c[2][8][4];
#pragma unroll
    for (int mi = 0; mi < 2; mi++)
#pragma unroll
        for (int ni = 0; ni < 8; ni++)
#pragma unroll
            for (int j = 0; j < 4; j++) c[mi][ni][j] = 0.f;

    auto issue = [&](int ch, uint32_t sbase) {
        const int k4 = ch * 8;
#pragma unroll
        for (int it = 0; it < 8; it++) {
            int slot = it * 256 + tid, row = slot >> 3, seg = slot & 7;
            if (row < 128) {                   // A rows
                bool ok = (r0 + row) < R;
                const uint4* src = Xb + (ok ? (size_t)(r0 + row) * 96 : 0) + k4 + seg;
                cp16(sbase + (uint32_t)(row * PPITCH + seg * 16), src, ok);
            } else {                           // W rows
                int wr = row - 128;
                const uint4* src = Wb + (size_t)(e0 + wr) * 96 + k4 + seg;
                cp16(sbase + (uint32_t)(PBOFF + wr * PPITCH + seg * 16), src, true);
            }
        }
    };

    issue(0, st0); CP_COMMIT();
    issue(1, st1); CP_COMMIT();

    for (int ch = 0; ch < 12; ch++) {
        if (ch == 11) asm volatile("cp.async.wait_group 0;" ::: "memory");
        else          asm volatile("cp.async.wait_group 1;" ::: "memory");
        __syncthreads();

        const uint32_t sb = (ch & 1) ? st1 : st0;
        const uint32_t aa = sb + aoff, ba = sb + boff;
#pragma unroll
        for (int ks = 0; ks < 4; ks++) {
            uint32_t af[2][4], bf[16];
#pragma unroll
            for (int mi = 0; mi < 2; mi++)
                ldmatrix_x4(af[mi], aa + mi * (16 * PPITCH) + ks * 32);
#pragma unroll
            for (int nn = 0; nn < 4; nn++)
                ldmatrix_x4(bf + nn * 4, ba + nn * (16 * PPITCH) + ks * 32);
#pragma unroll
            for (int mi = 0; mi < 2; mi++)
#pragma unroll
                for (int ni = 0; ni < 8; ni++)
                    mma_16816(c[mi][ni], af[mi], bf + ni * 2);
        }
        __syncthreads();
        if (ch + 2 < 12) { issue(ch + 2, sb); CP_COMMIT(); }
    }

#pragma unroll
    for (int mi = 0; mi < 2; mi++) {
        int rr = r0 + mrow + mi * 16 + (lane >> 2);
        if (rr < R) {
#pragma unroll
            for (int ni = 0; ni < 8; ni++) {
                int e = e0 + ncol + ni * 8 + ((lane & 3) << 1);
                float2 o;
                o.x = c[mi][ni][0] + bias[e];
                o.y = c[mi][ni][1] + bias[e + 1];
                *(float2*)(Y + (size_t)rr * NE + e) = o;
                o.x = c[mi][ni][2] + bias[e];
                o.y = c[mi][ni][3] + bias[e + 1];
                *(float2*)(Y + (size_t)(rr + 8) * NE + e) = o;
            }
        }
    }
}

// ===========================================================================
// L2-normalize rows (fp32 in), write bf16 operand buffers
// ===========================================================================
__global__ __launch_bounds__(256) void l2norm_rows()
{
    const int NROWS_V = NB * NV;
    const int NROWS = NROWS_V + NQ * NT;
    int row = blockIdx.x * 8 + (threadIdx.x >> 5);
    int lane = threadIdx.x & 31;
    if (row >= NROWS) return;
    const float* src;
    __nv_bfloat16* dst;
    if (row < NROWS_V) {
        src = g_vtok_f32 + (size_t)row * NE;
        dst = g_vtok + (size_t)row * NE;
    } else {
        src = g_ttok_f32 + (size_t)(row - NROWS_V) * NE;
        dst = g_ttok + (size_t)(row - NROWS_V) * NE;
    }
    const float4* p4 = (const float4*)src;
    float s = 0.f;
#pragma unroll
    for (int i = lane; i < NE / 4; i += 32) {
        float4 v = p4[i];
        s += v.x * v.x + v.y * v.y + v.z * v.z + v.w * v.w;
    }
#pragma unroll
    for (int off = 16; off > 0; off >>= 1)
        s += __shfl_xor_sync(0xffffffffu, s, off);
    float inv = 1.f / fmaxf(sqrtf(s), 1e-12f);
    __nv_bfloat162* d2 = (__nv_bfloat162*)dst;
#pragma unroll
    for (int i = lane; i < NE / 4; i += 32) {
        float4 v = p4[i];
        d2[2 * i]     = __float22bfloat162_rn(make_float2(v.x * inv, v.y * inv));
        d2[2 * i + 1] = __float22bfloat162_rn(make_float2(v.z * inv, v.w * inv));
    }
}

// ===========================================================================
// Stage 2: one CTA = (b, q-pair). 3-stage cp.async, register/shfl epilogue.
// ===========================================================================
#define APITCH 144
#define BOFF2  (256 * APITCH)
#define STAGE  (BOFF2 + 160 * APITCH)
#define SMEM_DYN (3 * STAGE)
#define NINF   (-INFINITY)

__global__ __launch_bounds__(512, 1) void stage2(
    const int* __restrict__ text_length,
    float* __restrict__ t2v, float* __restrict__ v2t)
{
    extern __shared__ __align__(16) char dsm[];
    __shared__ float s_colmax[8][164];
    __shared__ float s_vsum[16];
    __shared__ float s_tred[256];

    const int tid = threadIdx.x;
    const int wid = tid >> 5, lane = tid & 31;
    const int qb = blockIdx.x, b = blockIdx.y;

    const int len0 = text_length[2 * qb];
    const int len1 = text_length[2 * qb + 1];

    const uint4* Va  = (const uint4*)(g_vtok + (size_t)b * NV * NE);
    const uint4* Tt0 = (const uint4*)(g_ttok + (size_t)(2 * qb) * NT * NE);
    const uint4* Tt1 = (const uint4*)(g_ttok + (size_t)(2 * qb + 1) * NT * NE);

    const uint32_t st[3] = { smem_u32(dsm), smem_u32(dsm) + STAGE,
                             smem_u32(dsm) + 2 * STAGE };

    const int mrow = (wid & 7) * 32;
    const int myq  = wid >> 3;
    const int ncol = myq * 80;

    const uint32_t aoff = (uint32_t)(mrow + (lane & 7) + ((lane >> 3) & 1) * 8) * APITCH
                        + (uint32_t)(lane >> 4) * 16;
    const uint32_t boff = BOFF2
                        + (uint32_t)(ncol + (lane & 7) + ((lane >> 4) << 3)) * APITCH
                        + (uint32_t)((lane >> 3) & 1) * 16;

    float c[2][10][4];
#pragma unroll
    for (int mi = 0; mi < 2; mi++)
#pragma unroll
        for (int ni = 0; ni < 10; ni++)
#pragma unroll
            for (int j = 0; j < 4; j++) c[mi][ni][j] = 0.f;

    auto issue = [&](int ch, uint32_t sbase) {
        const int k4 = ch * 8;
#pragma unroll
        for (int it = 0; it < 4; it++) {
            int slot = it * 512 + tid, row = slot >> 3, seg = slot & 7;
            bool ok = row < NV;
            const uint4* src = Va + (ok ? row * 64 : 0) + k4 + seg;
            cp16(sbase + (uint32_t)(row * APITCH + seg * 16), src, ok);
        }
#pragma unroll
        for (int it = 0; it < 3; it++) {
            int slot = it * 512 + tid;
            if (slot < 1280) {
                int rbb = slot >> 3, seg = slot & 7;
                int trow = (rbb < 80) ? rbb : rbb - 80;
                bool ok = trow < NT;
                const uint4* base = (rbb < 80) ? Tt0 : Tt1;
                const uint4* src = base + (ok ? trow * 64 : 0) + k4 + seg;
                cp16(sbase + (uint32_t)(BOFF2 + rbb * APITCH + seg * 16), src, ok);
            }
        }
    };

    issue(0, st[0]); CP_COMMIT();
    issue(1, st[1]); CP_COMMIT();
    issue(2, st[2]); CP_COMMIT();

    for (int ch = 0; ch < 8; ch++) {
        if (ch < 6)       asm volatile("cp.async.wait_group 2;" ::: "memory");
        else if (ch == 6) asm volatile("cp.async.wait_group 1;" ::: "memory");
        else              asm volatile("cp.async.wait_group 0;" ::: "memory");
        __syncthreads();

        const uint32_t sb = st[ch % 3];
        const uint32_t aa = sb + aoff, ba = sb + boff;
#pragma unroll
        for (int ks = 0; ks < 4; ks++) {
            uint32_t af[2][4], bf[20];
#pragma unroll
            for (int mi = 0; mi < 2; mi++)
                ldmatrix_x4(af[mi], aa + mi * (16 * APITCH) + ks * 32);
#pragma unroll
            for (int nn = 0; nn < 5; nn++)
                ldmatrix_x4(bf + nn * 4, ba + nn * (16 * APITCH) + ks * 32);
#pragma unroll
            for (int mi = 0; mi < 2; mi++)
#pragma unroll
                for (int ni = 0; ni < 10; ni++)
                    mma_16816(c[mi][ni], af[mi], bf + ni * 2);
        }
        __syncthreads();
        if (ch + 3 < 8) { issue(ch + 3, sb); CP_COMMIT(); }
    }

    // ---- register/shfl epilogue ----
    const int mylen = myq ? len1 : len0;
    const int rb = mrow + (lane >> 2);

    float rowmax[2][2] = {{NINF, NINF}, {NINF, NINF}};
    float colmax[10][2];
#pragma unroll
    for (int ni = 0; ni < 10; ni++) { colmax[ni][0] = NINF; colmax[ni][1] = NINF; }

#pragma unroll
    for (int mi = 0; mi < 2; mi++) {
        int r0 = rb + mi * 16;
        bool v0 = r0 < NV, v8 = (r0 + 8) < NV;
#pragma unroll
        for (int ni = 0; ni < 10; ni++) {
            int tl = ni * 8 + ((lane & 3) << 1);
            float* cf = c[mi][ni];
            float m0 = (tl     < mylen) ? cf[0] : ((tl     < NT) ? 0.f : NINF);
            float m1 = (tl + 1 < mylen) ? cf[1] : ((tl + 1 < NT) ? 0.f : NINF);
            float m2 = (tl     < mylen) ? cf[2] : ((tl     < NT) ? 0.f : NINF);
            float m3 = (tl + 1 < mylen) ? cf[3] : ((tl + 1 < NT) ? 0.f : NINF);
            rowmax[mi][0] = fmaxf(rowmax[mi][0], fmaxf(m0, m1));
            rowmax[mi][1] = fmaxf(rowmax[mi][1], fmaxf(m2, m3));
            colmax[ni][0] = fmaxf(colmax[ni][0],
                fmaxf(v0 ? cf[0] : NINF, v8 ? cf[2] : NINF));
            colmax[ni][1] = fmaxf(colmax[ni][1],
                fmaxf(v0 ? cf[1] : NINF, v8 ? cf[3] : NINF));
        }
    }

#pragma unroll
    for (int mi = 0; mi < 2; mi++)
#pragma unroll
        for (int h = 0; h < 2; h++) {
            float r = rowmax[mi][h];
            r = fmaxf(r, __shfl_xor_sync(0xffffffffu, r, 1));
            r = fmaxf(r, __shfl_xor_sync(0xffffffffu, r, 2));
            rowmax[mi][h] = r;
        }
    float rowsum = 0.f;
#pragma unroll
    for (int mi = 0; mi < 2; mi++) {
        int r0 = rb + mi * 16;
        if (r0 < NV)     rowsum += rowmax[mi][0];
        if (r0 + 8 < NV) rowsum += rowmax[mi][1];
    }
    rowsum += __shfl_xor_sync(0xffffffffu, rowsum, 4);
    rowsum += __shfl_xor_sync(0xffffffffu, rowsum, 8);
    rowsum += __shfl_xor_sync(0xffffffffu, rowsum, 16);
    if (lane == 0) s_vsum[wid] = rowsum;

#pragma unroll
    for (int ni = 0; ni < 10; ni++)
#pragma unroll
        for (int h = 0; h < 2; h++) {
            float r = colmax[ni][h];
            r = fmaxf(r, __shfl_xor_sync(0xffffffffu, r, 4));
            r = fmaxf(r, __shfl_xor_sync(0xffffffffu, r, 8));
            r = fmaxf(r, __shfl_xor_sync(0xffffffffu, r, 16));
            colmax[ni][h] = r;
        }
    if (lane < 4) {
#pragma unroll
        for (int ni = 0; ni < 10; ni++) {
            int cc = ncol + ni * 8 + (lane << 1);
            s_colmax[wid & 7][cc]     = colmax[ni][0];
            s_colmax[wid & 7][cc + 1] = colmax[ni][1];
        }
    }
    __syncthreads();

    if (tid < 256) {
        int qq = tid >> 7, cl = tid & 127;
        float val = 0.f;
        if (cl < 80) {
            float cm = NINF;
#pragma unroll
            for (int w = 0; w < 8; w++) cm = fmaxf(cm, s_colmax[w][qq * 80 + cl]);
            int len = qq ? len1 : len0;
            val = (cl < len) ? cm : 0.f;
        }
        s_tred[tid] = val;
    }
    __syncthreads();
#pragma unroll
    for (int s = 64; s > 0; s >>= 1) {
        if (tid < 256 && (tid & 127) < s) s_tred[tid] += s_tred[tid + s];
        __syncthreads();
    }
    if (tid == 0) {
        float v0s = 0.f, v1s = 0.f;
#pragma unroll
        for (int w = 0; w < 8; w++) { v0s += s_vsum[w]; v1s += s_vsum[8 + w]; }
        t2v[b * NQ + 2 * qb]     = s_tred[0]   / (float)len0;
        t2v[b * NQ + 2 * qb + 1] = s_tred[128] / (float)len1;
        v2t[b * NQ + 2 * qb]     = v0s / (float)NV;
        v2t[b * NQ + 2 * qb + 1] = v1s / (float)NV;
    }
}

// ===========================================================================
extern "C" void kernel_launch(void* const* d_in, const int* in_sizes, int n_in,
                              void* d_out, int out_size)
{
    const float* visual_cls     = (const float*)d_in[0];
    const float* visual_tokens  = (const float*)d_in[1];
    const float* textual_cls    = (const float*)d_in[2];
    const float* textual_tokens = (const float*)d_in[3];
    const float* Wv_cls = (const float*)d_in[4];
    const float* bv_cls = (const float*)d_in[5];
    const float* Wt_cls = (const float*)d_in[6];
    const float* bt_cls = (const float*)d_in[7];
    const float* Wv_tok = (const float*)d_in[8];
    const float* bv_tok = (const float*)d_in[9];
    const float* Wt_tok = (const float*)d_in[10];
    const float* bt_tok = (const float*)d_in[11];
    const int*   text_length = (const int*)d_in[12];

    float* out = (float*)d_out;
    float* o_vcls = out;
    float* o_tcls = out + NB * NE;
    float* o_t2v  = out + 2 * NB * NE;
    float* o_v2t  = o_t2v + NB * NQ;

    // bf16 conversion of token GEMM operands
    {
        size_t n8 = CSEG3 / 8;
        int blocks = (int)((n8 + 255) / 256);
        convert_bf16<<<blocks, 256>>>(visual_tokens, textual_tokens, Wv_tok, Wt_tok);
    }

    // cls projections (one launch)
    proj_cls<<<dim3(2, 8, 2), 256>>>(visual_cls, Wv_cls, bv_cls, o_vcls,
                                     textual_cls, Wt_cls, bt_cls, o_tcls);

    // token projections (one launch, z = visual/textual)
    cudaFuncSetAttribute(proj_mma2, cudaFuncAttributeMaxDynamicSharedMemorySize,
                         2 * PSTAGE);
    proj_mma2<<<dim3(VIS_BX, 4, 2), 256, 2 * PSTAGE>>>(bv_tok, bt_tok);

    l2norm_rows<<<(NB * NV + NQ * NT + 7) / 8, 256>>>();

    cudaFuncSetAttribute(stage2, cudaFuncAttributeMaxDynamicSharedMemorySize, SMEM_DYN);
    stage2<<<dim3(NQ / 2, NB), 512, SMEM_DYN>>>(text_length, o_t2v, o_v2t);
}